// round 11
// baseline (speedup 1.0000x reference)
#include <cuda_runtime.h>
#include <cuda_bf16.h>
#include <cstdint>
#include <cstddef>

typedef unsigned long long ull;

// ---------------- scratch (device globals: no cudaMalloc allowed) ----------
__device__ __nv_bfloat16 g_from_hi[4194304];
__device__ __nv_bfloat16 g_to_hi[4194304], g_to_lo[4194304];
__device__ __nv_bfloat16 g_wq_hi[1048576];
__device__ __nv_bfloat16 g_wk_hi[1048576];
__device__ __nv_bfloat16 g_wv_hi[1048576], g_wv_lo[1048576];
__device__ __nv_bfloat16 g_wo_hi[1048576], g_wo_lo[1048576];
__device__ __nv_bfloat16 g_q[4194304];                    // single bf16
__device__ __nv_bfloat16 g_k[4194304];                    // single bf16
__device__ __nv_bfloat16 g_v_hi[4194304], g_v_lo[4194304];
__device__ __nv_bfloat16 g_c_hi[4194304], g_c_lo[4194304];
__device__ __nv_bfloat16 g_sb[67108864];                  // scores bf16 [B*N,S,S]
__device__ __nv_bfloat16 g_p_hi[67108864], g_p_lo[67108864];

// ---------------------------------------------------------------------------
// PTX helpers
// ---------------------------------------------------------------------------
__device__ __forceinline__ uint32_t smem_u32(const void* p) {
    return (uint32_t)__cvta_generic_to_shared(p);
}
__device__ __forceinline__ void ldsm_x4(uint32_t* r, uint32_t addr) {
    asm volatile("ldmatrix.sync.aligned.m8n8.x4.shared.b16 {%0,%1,%2,%3}, [%4];"
                 : "=r"(r[0]), "=r"(r[1]), "=r"(r[2]), "=r"(r[3]) : "r"(addr));
}
__device__ __forceinline__ void ldsm_x4_t(uint32_t* r, uint32_t addr) {
    asm volatile("ldmatrix.sync.aligned.m8n8.x4.trans.shared.b16 {%0,%1,%2,%3}, [%4];"
                 : "=r"(r[0]), "=r"(r[1]), "=r"(r[2]), "=r"(r[3]) : "r"(addr));
}
__device__ __forceinline__ void mma_bf16(float* c, const uint32_t* a, const uint32_t* b) {
    asm volatile(
        "mma.sync.aligned.m16n8k16.row.col.f32.bf16.bf16.f32 "
        "{%0,%1,%2,%3}, {%4,%5,%6,%7}, {%8,%9}, {%0,%1,%2,%3};"
        : "+f"(c[0]), "+f"(c[1]), "+f"(c[2]), "+f"(c[3])
        : "r"(a[0]), "r"(a[1]), "r"(a[2]), "r"(a[3]), "r"(b[0]), "r"(b[1]));
}
__device__ __forceinline__ void split_bf16(float x, __nv_bfloat16& h, __nv_bfloat16& l) {
    h = __float2bfloat16(x);
    l = __float2bfloat16(x - __bfloat162float(h));
}
__device__ __forceinline__ void cp16(uint32_t dst, const void* src) {
    asm volatile("cp.async.cg.shared.global [%0], [%1], 16;\n" :: "r"(dst), "l"(src));
}
#define CP_COMMIT() asm volatile("cp.async.commit_group;\n")
#define CP_WAIT(n)  asm volatile("cp.async.wait_group %0;\n" :: "n"(n))

// ---------------------------------------------------------------------------
// split helpers
// ---------------------------------------------------------------------------
__device__ __forceinline__ void do_split4(float4 v, uint2* hi, uint2* lo, int i, bool wlo) {
    if (wlo) {
        __nv_bfloat16 h0, h1, h2, h3, l0, l1, l2, l3;
        split_bf16(v.x, h0, l0); split_bf16(v.y, h1, l1);
        split_bf16(v.z, h2, l2); split_bf16(v.w, h3, l3);
        __nv_bfloat162 a = __halves2bfloat162(h0, h1), b = __halves2bfloat162(h2, h3);
        __nv_bfloat162 c = __halves2bfloat162(l0, l1), d = __halves2bfloat162(l2, l3);
        hi[i] = make_uint2(*(uint32_t*)&a, *(uint32_t*)&b);
        lo[i] = make_uint2(*(uint32_t*)&c, *(uint32_t*)&d);
    } else {
        __nv_bfloat162 a = __halves2bfloat162(__float2bfloat16(v.x), __float2bfloat16(v.y));
        __nv_bfloat162 b = __halves2bfloat162(__float2bfloat16(v.z), __float2bfloat16(v.w));
        hi[i] = make_uint2(*(uint32_t*)&a, *(uint32_t*)&b);
    }
}

__global__ void split_inputs(const float4* __restrict__ from, const float4* __restrict__ to,
                             uint2* __restrict__ fh, uint2* __restrict__ th, uint2* __restrict__ tl) {
    int i = blockIdx.x * 256 + threadIdx.x;
    if (i < 1048576) {
        do_split4(from[i], fh, nullptr, i, false);
    } else {
        int j = i - 1048576;
        do_split4(to[j], th, tl, j, true);
    }
}

__global__ void split_weights(const float4* __restrict__ wq, const float4* __restrict__ wk,
                              const float4* __restrict__ wv, const float4* __restrict__ wo,
                              uint2* __restrict__ qh, uint2* __restrict__ kh,
                              uint2* __restrict__ vh, uint2* __restrict__ vl,
                              uint2* __restrict__ oh, uint2* __restrict__ ol) {
    int i = blockIdx.x * 256 + threadIdx.x;
    int sel = i >> 18, j = i & 0x3FFFF;
    if (sel == 0)      do_split4(wq[j], qh, nullptr, j, false);
    else if (sel == 1) do_split4(wk[j], kh, nullptr, j, false);
    else if (sel == 2) do_split4(wv[j], vh, vl, j, true);
    else               do_split4(wo[j], oh, ol, j, true);
}

// ---------------------------------------------------------------------------
// GEMM (single-bf16, merged Q+K): block 128x128, BK=32, 3-stage.  Unchanged.
// smem per stage (elems): Ahi@0 (5120) Bhi@5120 (4352)  -> 9472
// ---------------------------------------------------------------------------
__device__ __forceinline__ void gemm1_stage(uint32_t sb,
        const __nv_bfloat16* Ahi, const __nv_bfloat16* Bhi,
        int row0, int col0, int k0, int tid) {
#pragma unroll
    for (int l = 0; l < 2; l++) {
        int idx = tid + l * 256;
        int m = idx >> 2, kc = (idx & 3) << 3;
        cp16(sb + (uint32_t)(m * 40 + kc) * 2,
             Ahi + (size_t)(row0 + m) * 1024 + k0 + kc);
    }
#pragma unroll
    for (int l = 0; l < 2; l++) {
        int idx = tid + l * 256;
        int k = idx >> 4, nc = (idx & 15) << 3;
        cp16(sb + (uint32_t)(5120 + k * 136 + nc) * 2,
             Bhi + (size_t)(k0 + k) * 1024 + col0 + nc);
    }
}

__global__ __launch_bounds__(256, 2)
void gemm_qk_proj(const __nv_bfloat16* __restrict__ A1, const __nv_bfloat16* __restrict__ B1,
                  const float* __restrict__ bias1, __nv_bfloat16* __restrict__ C1,
                  const __nv_bfloat16* __restrict__ A2, const __nv_bfloat16* __restrict__ B2,
                  const float* __restrict__ bias2, __nv_bfloat16* __restrict__ C2) {
    extern __shared__ __nv_bfloat16 dsm[];
    constexpr uint32_t PS = 9472;
    const __nv_bfloat16* Ahi = (blockIdx.z == 0) ? A1 : A2;
    const __nv_bfloat16* Bhi = (blockIdx.z == 0) ? B1 : B2;
    const float* bias        = (blockIdx.z == 0) ? bias1 : bias2;
    __nv_bfloat16* Chi       = (blockIdx.z == 0) ? C1 : C2;
    const int tid = threadIdx.x, lane = tid & 31, warp = tid >> 5;
    const int wm = warp >> 1, wn = warp & 1;
    const int row0 = blockIdx.y * 128, col0 = blockIdx.x * 128;
    const uint32_t sbase = smem_u32(dsm);

    float c[2][8][4];
#pragma unroll
    for (int i = 0; i < 2; i++)
#pragma unroll
        for (int j = 0; j < 8; j++)
#pragma unroll
            for (int q = 0; q < 4; q++) c[i][j][q] = 0.0f;

    gemm1_stage(sbase,          Ahi, Bhi, row0, col0, 0,  tid);
    CP_COMMIT();
    gemm1_stage(sbase + PS * 2, Ahi, Bhi, row0, col0, 32, tid);
    CP_COMMIT();

    const int lrow = lane & 15, koff = (lane >> 4) << 3;
    int st = 0;
    for (int k0 = 0; k0 < 1024; k0 += 32) {
        if (k0 + 32 < 1024) { CP_WAIT(1); } else { CP_WAIT(0); }
        __syncthreads();

        const uint32_t sb = sbase + (uint32_t)st * PS * 2;
#pragma unroll
        for (int ks = 0; ks < 2; ks++) {
            uint32_t ahi[2][4];
#pragma unroll
            for (int mf = 0; mf < 2; mf++) {
                uint32_t off = (uint32_t)((wm * 32 + mf * 16 + lrow) * 40 + ks * 16 + koff) * 2;
                ldsm_x4(ahi[mf], sb + off);
            }
#pragma unroll
            for (int g = 0; g < 4; g++) {
                uint32_t bh[4];
                uint32_t off = (uint32_t)((ks * 16 + lrow) * 136 + wn * 64 + g * 16 + koff) * 2;
                ldsm_x4_t(bh, sb + 5120 * 2 + off);
#pragma unroll
                for (int h = 0; h < 2; h++) {
                    int nf = g * 2 + h;
#pragma unroll
                    for (int mf = 0; mf < 2; mf++)
                        mma_bf16(c[mf][nf], ahi[mf], bh + h * 2);
                }
            }
        }
        if (k0 + 64 < 1024) {
            int nst = (st + 2 > 2) ? (st - 1) : (st + 2);
            gemm1_stage(sbase + (uint32_t)nst * PS * 2, Ahi, Bhi, row0, col0, k0 + 64, tid);
            CP_COMMIT();
        }
        st = (st == 2) ? 0 : st + 1;
    }

    const int rbase = row0 + wm * 32 + (lane >> 2);
    const int cbase = col0 + wn * 64 + (lane & 3) * 2;
#pragma unroll
    for (int mf = 0; mf < 2; mf++) {
#pragma unroll
        for (int nf = 0; nf < 8; nf++) {
            int r = rbase + mf * 16;
            int cc = cbase + nf * 8;
            float2 bv = *(const float2*)(bias + cc);
            *(__nv_bfloat162*)(Chi + (size_t)r * 1024 + cc) =
                __halves2bfloat162(__float2bfloat16(c[mf][nf][0] + bv.x),
                                   __float2bfloat16(c[mf][nf][1] + bv.y));
            *(__nv_bfloat162*)(Chi + (size_t)(r + 8) * 1024 + cc) =
                __halves2bfloat162(__float2bfloat16(c[mf][nf][2] + bv.x),
                                   __float2bfloat16(c[mf][nf][3] + bv.y));
        }
    }
}

// ---------------------------------------------------------------------------
// GEMM bf16x3, HIGH-OCCUPANCY: block 64x128, BK=32, 2-stage, 3 CTAs/SM.
// 8 warps as 2m x 4n (warp tile 32x32).  MODE: 0 = fp32 out, 1 = split out.
// smem per stage (elems): Ahi@0 (2560) Alo@2560 Bhi@5120 (4352) Blo@9472 -> 13824
// ---------------------------------------------------------------------------
#define G3_PS 13824
__device__ __forceinline__ void gemm3_stage(uint32_t sb,
        const __nv_bfloat16* Ahi, const __nv_bfloat16* Alo,
        const __nv_bfloat16* Bhi, const __nv_bfloat16* Blo,
        int row0, int col0, int k0, int tid) {
    {
        int m = tid >> 2, kc = (tid & 3) << 3;
        size_t so = (size_t)(row0 + m) * 1024 + k0 + kc;
        cp16(sb + (uint32_t)(m * 40 + kc) * 2, Ahi + so);
        cp16(sb + (uint32_t)(2560 + m * 40 + kc) * 2, Alo + so);
    }
#pragma unroll
    for (int l = 0; l < 2; l++) {
        int idx = tid + l * 256;
        int k = idx >> 4, nc = (idx & 15) << 3;
        size_t so = (size_t)(k0 + k) * 1024 + col0 + nc;
        cp16(sb + (uint32_t)(5120 + k * 136 + nc) * 2, Bhi + so);
        cp16(sb + (uint32_t)(9472 + k * 136 + nc) * 2, Blo + so);
    }
}

template <int MODE>
__global__ __launch_bounds__(256, 3)
void gemm3_64(const __nv_bfloat16* __restrict__ Ahi, const __nv_bfloat16* __restrict__ Alo,
              const __nv_bfloat16* __restrict__ Bhi, const __nv_bfloat16* __restrict__ Blo,
              const float* __restrict__ bias,
              float* __restrict__ Cf,
              __nv_bfloat16* __restrict__ Chi, __nv_bfloat16* __restrict__ Clo) {
    extern __shared__ __nv_bfloat16 dsm[];
    const int tid = threadIdx.x, lane = tid & 31, warp = tid >> 5;
    const int wm = warp >> 2, wn = warp & 3;      // 2m x 4n
    const int row0 = blockIdx.y * 64, col0 = blockIdx.x * 128;
    const uint32_t sbase = smem_u32(dsm);

    float c[2][4][4];
#pragma unroll
    for (int i = 0; i < 2; i++)
#pragma unroll
        for (int j = 0; j < 4; j++)
#pragma unroll
            for (int q = 0; q < 4; q++) c[i][j][q] = 0.0f;

    gemm3_stage(sbase, Ahi, Alo, Bhi, Blo, row0, col0, 0, tid);
    CP_COMMIT();

    const int lrow = lane & 15, koff = (lane >> 4) << 3;
    int st = 0;
    for (int k0 = 0; k0 < 1024; k0 += 32, st ^= 1) {
        if (k0 + 32 < 1024) {
            gemm3_stage(sbase + (uint32_t)(st ^ 1) * G3_PS * 2, Ahi, Alo, Bhi, Blo,
                        row0, col0, k0 + 32, tid);
            CP_COMMIT();
            CP_WAIT(1);
        } else {
            CP_WAIT(0);
        }
        __syncthreads();

        const uint32_t sb = sbase + (uint32_t)st * G3_PS * 2;
#pragma unroll
        for (int ks = 0; ks < 2; ks++) {
            uint32_t ahi[2][4], alo[2][4];
#pragma unroll
            for (int mf = 0; mf < 2; mf++) {
                uint32_t off = (uint32_t)((wm * 32 + mf * 16 + lrow) * 40 + ks * 16 + koff) * 2;
                ldsm_x4(ahi[mf], sb + off);
                ldsm_x4(alo[mf], sb + 2560 * 2 + off);
            }
#pragma unroll
            for (int g = 0; g < 2; g++) {
                uint32_t bh[4], bl[4];
                uint32_t off = (uint32_t)((ks * 16 + lrow) * 136 + wn * 32 + g * 16 + koff) * 2;
                ldsm_x4_t(bh, sb + 5120 * 2 + off);
                ldsm_x4_t(bl, sb + 9472 * 2 + off);
#pragma unroll
                for (int h = 0; h < 2; h++) {
                    int nf = g * 2 + h;
#pragma unroll
                    for (int mf = 0; mf < 2; mf++) {
                        mma_bf16(c[mf][nf], ahi[mf], bh + h * 2);
                        mma_bf16(c[mf][nf], ahi[mf], bl + h * 2);
                        mma_bf16(c[mf][nf], alo[mf], bh + h * 2);
                    }
                }
            }
        }
        __syncthreads();
    }

    const int rbase = row0 + wm * 32 + (lane >> 2);
    const int cbase = col0 + wn * 32 + (lane & 3) * 2;
#pragma unroll
    for (int mf = 0; mf < 2; mf++) {
#pragma unroll
        for (int nf = 0; nf < 4; nf++) {
            int r = rbase + mf * 16;
            int cc = cbase + nf * 8;
            float2 bv = *(const float2*)(bias + cc);
            float v00 = c[mf][nf][0] + bv.x, v01 = c[mf][nf][1] + bv.y;
            float v10 = c[mf][nf][2] + bv.x, v11 = c[mf][nf][3] + bv.y;
            if (MODE == 1) {
                __nv_bfloat16 h0, l0, h1, l1;
                split_bf16(v00, h0, l0); split_bf16(v01, h1, l1);
                *(__nv_bfloat162*)(Chi + (size_t)r * 1024 + cc) = __halves2bfloat162(h0, h1);
                *(__nv_bfloat162*)(Clo + (size_t)r * 1024 + cc) = __halves2bfloat162(l0, l1);
                split_bf16(v10, h0, l0); split_bf16(v11, h1, l1);
                *(__nv_bfloat162*)(Chi + (size_t)(r + 8) * 1024 + cc) = __halves2bfloat162(h0, h1);
                *(__nv_bfloat162*)(Clo + (size_t)(r + 8) * 1024 + cc) = __halves2bfloat162(l0, l1);
            } else {
                *(float2*)(Cf + (size_t)r * 1024 + cc)       = make_float2(v00, v01);
                *(float2*)(Cf + (size_t)(r + 8) * 1024 + cc) = make_float2(v10, v11);
            }
        }
    }
}

// ---------------------------------------------------------------------------
// qk: scores[z,f,t] = 0.125 * sum_h q[..f,n,h] * k[..t,n,h], SINGLE bf16 MMA.
// ---------------------------------------------------------------------------
__global__ __launch_bounds__(256)
void qk_mma() {
    extern __shared__ __nv_bfloat16 dsm[];
    const int tid = threadIdx.x, lane = tid & 31, warp = tid >> 5;
    const int wm = warp >> 1, wn = warp & 1;
    const int z = blockIdx.z, b = z >> 4, n = z & 15;
    const int t0 = blockIdx.x * 128, f0 = blockIdx.y * 128;
    const uint32_t sbase = smem_u32(dsm);

    const size_t qoff = ((size_t)(b * 1024 + f0) * 16 + n) * 64;
    const size_t koffg = ((size_t)(b * 1024 + t0) * 16 + n) * 64;

#pragma unroll
    for (int l = 0; l < 4; l++) {
        int idx = tid + l * 256;
        int m = idx >> 3, hc = (idx & 7) << 3;
        size_t so = (size_t)m * 1024 + hc;
        uint32_t doff = (uint32_t)(m * 72 + hc) * 2;
        cp16(sbase + doff,            g_q + qoff + so);
        cp16(sbase + 9216 * 2 + doff, g_k + koffg + so);
    }
    CP_COMMIT();
    CP_WAIT(0);
    __syncthreads();

    float c[2][8][4];
#pragma unroll
    for (int i = 0; i < 2; i++)
#pragma unroll
        for (int j = 0; j < 8; j++)
#pragma unroll
            for (int q = 0; q < 4; q++) c[i][j][q] = 0.0f;

    const int lrow = lane & 15, koff = (lane >> 4) << 3;
#pragma unroll
    for (int ks = 0; ks < 4; ks++) {
        uint32_t a[2][4];
#pragma unroll
        for (int mf = 0; mf < 2; mf++) {
            uint32_t off = (uint32_t)((wm * 32 + mf * 16 + lrow) * 72 + ks * 16 + koff) * 2;
            ldsm_x4(a[mf], sbase + off);
        }
#pragma unroll
        for (int g = 0; g < 4; g++) {
            uint32_t rh[4];
            uint32_t off = (uint32_t)((wn * 64 + g * 16 + lrow) * 72 + ks * 16 + koff) * 2;
            ldsm_x4(rh, sbase + 9216 * 2 + off);
            uint32_t b0[2] = {rh[0], rh[2]}, b1[2] = {rh[1], rh[3]};
#pragma unroll
            for (int mf = 0; mf < 2; mf++) {
                mma_bf16(c[mf][g * 2 + 0], a[mf], b0);
                mma_bf16(c[mf][g * 2 + 1], a[mf], b1);
            }
        }
    }

    __nv_bfloat16* out = g_sb + (size_t)z * 1048576;
    const int rbase = f0 + wm * 32 + (lane >> 2);
    const int cbase = t0 + wn * 64 + (lane & 3) * 2;
#pragma unroll
    for (int mf = 0; mf < 2; mf++) {
#pragma unroll
        for (int nf = 0; nf < 8; nf++) {
            int r = rbase + mf * 16, cc = cbase + nf * 8;
            *(__nv_bfloat162*)(out + (size_t)r * 1024 + cc) =
                __halves2bfloat162(__float2bfloat16(c[mf][nf][0] * 0.125f),
                                   __float2bfloat16(c[mf][nf][1] * 0.125f));
            *(__nv_bfloat162*)(out + (size_t)(r + 8) * 1024 + cc) =
                __halves2bfloat162(__float2bfloat16(c[mf][nf][2] * 0.125f),
                                   __float2bfloat16(c[mf][nf][3] * 0.125f));
        }
    }
}

// ---------------------------------------------------------------------------
// fused premix(MMA) -> mask -> softmax -> postmix(FFMA).  (round-8 version)
// smem: sbf bf16[16][1032] (33024B) | s f32[16][1028] (65792B) | smadd[1024] (4096B)
// ---------------------------------------------------------------------------
#define SW 1028
#define SBFS 1032
__global__ __launch_bounds__(256)
void mix_softmax_kernel(const int* __restrict__ amask,
                        const float* __restrict__ pre,
                        const float* __restrict__ post) {
    extern __shared__ char dynsm[];
    __nv_bfloat16* sbf = (__nv_bfloat16*)dynsm;
    float* s     = (float*)(dynsm + 33024);
    float* smadd = (float*)(dynsm + 33024 + 65792);
    __shared__ float wpre[256], wpost[256], sinv[16];
    const int tid = threadIdx.x, lane = tid & 31, warp = tid >> 5;
    const int f = blockIdx.x, b = blockIdx.y;

    wpre[tid]  = pre[tid];
    wpost[tid] = post[tid];

    const size_t rowbase = ((size_t)(b * 16) * 1024 + f) * 1024;
    const uint32_t sbf_u32 = smem_u32(sbf);

#pragma unroll
    for (int l = 0; l < 8; l++) {
        int idx = tid + l * 256;
        int n = idx >> 7, ch = idx & 127;
        cp16(sbf_u32 + (uint32_t)(n * SBFS + ch * 8) * 2,
             g_sb + rowbase + (size_t)n * 1048576 + ch * 8);
    }
    CP_COMMIT();

    {
        int4 mv = *(const int4*)(amask + ((size_t)b * 1024 + f) * 1024 + tid * 4);
        smadd[tid * 4 + 0] = (1.0f - (float)mv.x) * -10000.0f;
        smadd[tid * 4 + 1] = (1.0f - (float)mv.y) * -10000.0f;
        smadd[tid * 4 + 2] = (1.0f - (float)mv.z) * -10000.0f;
        smadd[tid * 4 + 3] = (1.0f - (float)mv.w) * -10000.0f;
    }
    CP_WAIT(0);
    __syncthreads();

    // premix via MMA
    {
        const int g = lane >> 2, t4 = lane & 3;
        uint32_t awh[4], awl[4];
#pragma unroll
        for (int q = 0; q < 4; q++) {
            int kk = 2 * t4 + (q >> 1) * 8;
            int rr = g + (q & 1) * 8;
            __nv_bfloat16 h0, l0, h1, l1;
            split_bf16(wpre[kk * 16 + rr], h0, l0);
            split_bf16(wpre[(kk + 1) * 16 + rr], h1, l1);
            __nv_bfloat162 ph = __halves2bfloat162(h0, h1), pl = __halves2bfloat162(l0, l1);
            awh[q] = *(uint32_t*)&ph;
            awl[q] = *(uint32_t*)&pl;
        }
        const int t0 = warp * 128;
#pragma unroll
        for (int blk = 0; blk < 8; blk++) {
            int tb = t0 + blk * 16;
            uint32_t bfr[4];
            ldsm_x4_t(bfr, sbf_u32 + (uint32_t)((lane & 15) * SBFS + tb + ((lane >> 4) << 3)) * 2);
#pragma unroll
            for (int h = 0; h < 2; h++) {
                int cb = tb + h * 8 + 2 * t4;
                float m0 = smadd[cb], m1 = smadd[cb + 1];
                float c[4] = {m0, m1, m0, m1};
                mma_bf16(c, awh, bfr + h * 2);
                mma_bf16(c, awl, bfr + h * 2);
                *(float2*)&s[g * SW + cb]       = make_float2(c[0], c[1]);
                *(float2*)&s[(g + 8) * SW + cb] = make_float2(c[2], c[3]);
            }
        }
    }
    __syncthreads();

    // softmax
#pragma unroll
    for (int r = 0; r < 2; r++) {
        int l = warp * 2 + r;
        float m = -1e30f;
        for (int it = lane; it < 1024; it += 32) m = fmaxf(m, s[l * SW + it]);
#pragma unroll
        for (int o = 16; o > 0; o >>= 1) m = fmaxf(m, __shfl_xor_sync(0xffffffffu, m, o));
        float sum = 0.0f;
        for (int it = lane; it < 1024; it += 32) {
            float e = __expf(s[l * SW + it] - m);
            s[l * SW + it] = e;
            sum += e;
        }
#pragma unroll
        for (int o = 16; o > 0; o >>= 1) sum += __shfl_xor_sync(0xffffffffu, sum, o);
        if (lane == 0) sinv[l] = 1.0f / sum;
    }
    __syncthreads();

    // postmix (scalar FFMA), write split-bf16 P
#pragma unroll
    for (int c = 0; c < 2; c++) {
        int t = (tid + c * 256) * 2;
        float x0[16], x1[16];
#pragma unroll
        for (int n = 0; n < 16; n++) {
            x0[n] = s[n * SW + t] * sinv[n];
            x1[n] = s[n * SW + t + 1] * sinv[n];
        }
#pragma unroll
        for (int l = 0; l < 16; l++) {
            float y0 = 0.0f, y1 = 0.0f;
#pragma unroll
            for (int n = 0; n < 16; n++) {
                y0 = fmaf(x0[n], wpost[n * 16 + l], y0);
                y1 = fmaf(x1[n], wpost[n * 16 + l], y1);
            }
            __nv_bfloat16 h0, l0, h1, l1;
            split_bf16(y0, h0, l0); split_bf16(y1, h1, l1);
            size_t base = rowbase + (size_t)l * 1048576 + t;
            *(__nv_bfloat162*)(g_p_hi + base) = __halves2bfloat162(h0, h1);
            *(__nv_bfloat162*)(g_p_lo + base) = __halves2bfloat162(l0, l1);
        }
    }
}

// ---------------------------------------------------------------------------
// pv: ctx[b,f,n,h] = sum_t P[z,f,t] * v[b,t,n,h], bf16x3 MMA (P,V split).
// Block = 128f x 64h, BK=32, 2-stage (high occupancy: 3 CTAs/SM).
// ---------------------------------------------------------------------------
#define PV_PS 14848
__device__ __forceinline__ void pv_stage(uint32_t sb, size_t pbase, size_t vbase,
                                         int k0, int tid) {
#pragma unroll
    for (int l = 0; l < 2; l++) {
        int idx = tid + l * 256;
        int m = idx >> 2, tc = (idx & 3) << 3;
        size_t so = pbase + (size_t)m * 1024 + k0 + tc;
        cp16(sb + (uint32_t)(m * 40 + tc) * 2, g_p_hi + so);
        cp16(sb + (uint32_t)(5120 + m * 40 + tc) * 2, g_p_lo + so);
    }
    {
        int tr = tid >> 3, hc = (tid & 7) << 3;
        size_t so = vbase + (size_t)(k0 + tr) * 1024 + hc;
        cp16(sb + (uint32_t)(10240 + tr * 72 + hc) * 2, g_v_hi + so);
        cp16(sb + (uint32_t)(12544 + tr * 72 + hc) * 2, g_v_lo + so);
    }
}

__global__ __launch_bounds__(256, 3)
void pv_mma() {
    extern __shared__ __nv_bfloat16 dsm[];
    const int tid = threadIdx.x, lane = tid & 31, warp = tid >> 5;
    const int wm = warp >> 1, wn = warp & 1;
    const int z = blockIdx.y, b = z >> 4, n = z & 15;
    const int f0 = blockIdx.x * 128;
    const uint32_t sbase = smem_u32(dsm);

    const size_t pbase = (size_t)z * 1048576 + (size_t)f0 * 1024;
    const size_t vbase = (size_t)(b * 1024) * 1024 + (size_t)n * 64;

    float c[2][4][4];
#pragma unroll
    for (int i = 0; i < 2; i++)
#pragma unroll
        for (int j = 0; j < 4; j++)
#pragma unroll
            for (int q = 0; q < 4; q++) c[i][j][q] = 0.0f;

    pv_stage(sbase, pbase, vbase, 0, tid);
    CP_COMMIT();

    const int lrow = lane & 15, koff = (lane >> 4) << 3;
    int st = 0;
    for (int k0 = 0; k0 < 1024; k0 += 32, st ^= 1) {
        if (k0 + 32 < 1024) {
            pv_stage(sbase + (uint32_t)(st ^ 1) * PV_PS * 2, pbase, vbase, k0 + 32, tid);
            CP_COMMIT();
            CP_WAIT(1);
        } else {
            CP_WAIT(0);
        }
        __syncthreads();

        const uint32_t sb = sbase + (uint32_t)st * PV_PS * 2;
#pragma unroll
        for (int ks = 0; ks < 2; ks++) {
            uint32_t ahi[2][4], alo[2][4];
#pragma unroll
            for (int mf = 0; mf < 2; mf++) {
                uint32_t off = (uint32_t)((wm * 32 + mf * 16 + lrow) * 40 + ks * 16 + koff) * 2;
                ldsm_x4(ahi[mf], sb + off);
                ldsm_x4(alo[mf], sb + 5120 * 2 + off);
            }
#pragma unroll
            for (int g = 0; g < 2; g++) {
                uint32_t bh[4], bl[4];
                uint32_t off = (uint32_t)((ks * 16 + lrow) * 72 + wn * 32 + g * 16 + koff) * 2;
                ldsm_x4_t(bh, sb + 10240 * 2 + off);
                ldsm_x4_t(bl, sb + 12544 * 2 + off);
#pragma unroll
                for (int h = 0; h < 2; h++) {
                    int nf = g * 2 + h;
#pragma unroll
                    for (int mf = 0; mf < 2; mf++) {
                        mma_bf16(c[mf][nf], ahi[mf], bh + h * 2);
                        mma_bf16(c[mf][nf], ahi[mf], bl + h * 2);
                        mma_bf16(c[mf][nf], alo[mf], bh + h * 2);
                    }
                }
            }
        }
        __syncthreads();
    }

    const int rbase = f0 + wm * 32 + (lane >> 2);
    const int cbase = wn * 32 + (lane & 3) * 2;
#pragma unroll
    for (int mf = 0; mf < 2; mf++) {
#pragma unroll
        for (int nf = 0; nf < 4; nf++) {
            int r = rbase + mf * 16, cc = cbase + nf * 8;
            size_t o0 = ((size_t)(b * 1024 + r) * 16 + n) * 64 + cc;
            size_t o1 = ((size_t)(b * 1024 + r + 8) * 16 + n) * 64 + cc;
            __nv_bfloat16 h0, l0, h1, l1;
            split_bf16(c[mf][nf][0], h0, l0); split_bf16(c[mf][nf][1], h1, l1);
            *(__nv_bfloat162*)(g_c_hi + o0) = __halves2bfloat162(h0, h1);
            *(__nv_bfloat162*)(g_c_lo + o0) = __halves2bfloat162(l0, l1);
            split_bf16(c[mf][nf][2], h0, l0); split_bf16(c[mf][nf][3], h1, l1);
            *(__nv_bfloat162*)(g_c_hi + o1) = __halves2bfloat162(h0, h1);
            *(__nv_bfloat162*)(g_c_lo + o1) = __halves2bfloat162(l0, l1);
        }
    }
}

// ---------------------------------------------------------------------------
extern "C" void kernel_launch(void* const* d_in, const int* in_sizes, int n_in,
                              void* d_out, int out_size) {
    const float* from  = (const float*)d_in[0];
    const float* to    = (const float*)d_in[1];
    const int*   amask = (const int*)d_in[2];
    const float* wq    = (const float*)d_in[3];
    const float* bq    = (const float*)d_in[4];
    const float* wk    = (const float*)d_in[5];
    const float* bk    = (const float*)d_in[6];
    const float* wv    = (const float*)d_in[7];
    const float* bv    = (const float*)d_in[8];
    const float* pre   = (const float*)d_in[9];
    const float* post  = (const float*)d_in[10];
    const float* wo    = (const float*)d_in[11];
    const float* bo    = (const float*)d_in[12];
    float* out = (float*)d_out;

    void *fh, *th, *tl, *qwh, *kwh, *vwh, *vwl, *owh, *owl;
    void *qp, *kp, *vh, *vl, *ch, *cl;
    cudaGetSymbolAddress(&fh, g_from_hi);
    cudaGetSymbolAddress(&th, g_to_hi);   cudaGetSymbolAddress(&tl, g_to_lo);
    cudaGetSymbolAddress(&qwh, g_wq_hi);
    cudaGetSymbolAddress(&kwh, g_wk_hi);
    cudaGetSymbolAddress(&vwh, g_wv_hi);  cudaGetSymbolAddress(&vwl, g_wv_lo);
    cudaGetSymbolAddress(&owh, g_wo_hi);  cudaGetSymbolAddress(&owl, g_wo_lo);
    cudaGetSymbolAddress(&qp, g_q);       cudaGetSymbolAddress(&kp, g_k);
    cudaGetSymbolAddress(&vh, g_v_hi);    cudaGetSymbolAddress(&vl, g_v_lo);
    cudaGetSymbolAddress(&ch, g_c_hi);    cudaGetSymbolAddress(&cl, g_c_lo);

    const int QKP_SMEM = 3 * 9472 * 2;        // 56832 B
    const int G3_SMEM  = 2 * G3_PS * 2;       // 55296 B -> 3 CTAs/SM
    const int QK_SMEM  = 18432 * 2;           // 36864 B
    const int PV_SMEM  = 2 * PV_PS * 2;       // 59392 B -> 3 CTAs/SM
    const int SMX_SMEM = 33024 + 65792 + 4096;  // 102912 B -> 2 CTAs/SM
    cudaFuncSetAttribute((const void*)gemm_qk_proj,       cudaFuncAttributeMaxDynamicSharedMemorySize, QKP_SMEM);
    cudaFuncSetAttribute((const void*)gemm3_64<0>,        cudaFuncAttributeMaxDynamicSharedMemorySize, G3_SMEM);
    cudaFuncSetAttribute((const void*)gemm3_64<1>,        cudaFuncAttributeMaxDynamicSharedMemorySize, G3_SMEM);
    cudaFuncSetAttribute((const void*)qk_mma,             cudaFuncAttributeMaxDynamicSharedMemorySize, QK_SMEM);
    cudaFuncSetAttribute((const void*)pv_mma,             cudaFuncAttributeMaxDynamicSharedMemorySize, PV_SMEM);
    cudaFuncSetAttribute((const void*)mix_softmax_kernel, cudaFuncAttributeMaxDynamicSharedMemorySize, SMX_SMEM);

    split_inputs<<<8192, 256>>>((const float4*)from, (const float4*)to,
                                (uint2*)fh, (uint2*)th, (uint2*)tl);
    split_weights<<<4096, 256>>>((const float4*)wq, (const float4*)wk,
                                 (const float4*)wv, (const float4*)wo,
                                 (uint2*)qwh, (uint2*)kwh,
                                 (uint2*)vwh, (uint2*)vwl,
                                 (uint2*)owh, (uint2*)owl);

    // merged Q+K projections (z=0 -> Q, z=1 -> K), single bf16
    gemm_qk_proj<<<dim3(8, 32, 2), 256, QKP_SMEM>>>(
        (const __nv_bfloat16*)fh, (const __nv_bfloat16*)qwh, bq, (__nv_bfloat16*)qp,
        (const __nv_bfloat16*)th, (const __nv_bfloat16*)kwh, bk, (__nv_bfloat16*)kp);

    // V projection: full bf16x3, high-occupancy 64x128 tiles
    gemm3_64<1><<<dim3(8, 64), 256, G3_SMEM>>>(
        (const __nv_bfloat16*)th, (const __nv_bfloat16*)tl,
        (const __nv_bfloat16*)vwh, (const __nv_bfloat16*)vwl, bv,
        nullptr, (__nv_bfloat16*)vh, (__nv_bfloat16*)vl);

    qk_mma<<<dim3(8, 8, 64), 256, QK_SMEM>>>();

    mix_softmax_kernel<<<dim3(1024, 4), 256, SMX_SMEM>>>(amask, pre, post);

    pv_mma<<<dim3(8, 64), 256, PV_SMEM>>>();

    // out projection: full bf16x3, high-occupancy 64x128 tiles
    gemm3_64<0><<<dim3(8, 64), 256, G3_SMEM>>>(
        (const __nv_bfloat16*)ch, (const __nv_bfloat16*)cl,
        (const __nv_bfloat16*)owh, (const __nv_bfloat16*)owl, bo,
        out, nullptr, nullptr);
}

// round 12
// speedup vs baseline: 1.0919x; 1.0919x over previous
#include <cuda_runtime.h>
#include <cuda_bf16.h>
#include <cstdint>
#include <cstddef>

typedef unsigned long long ull;

// ---------------- scratch (device globals: no cudaMalloc allowed) ----------
__device__ __nv_bfloat16 g_from_hi[4194304];
__device__ __nv_bfloat16 g_to_hi[4194304], g_to_lo[4194304];
__device__ __nv_bfloat16 g_wq_hi[1048576];
__device__ __nv_bfloat16 g_wk_hi[1048576];
__device__ __nv_bfloat16 g_wv_hi[1048576], g_wv_lo[1048576];
__device__ __nv_bfloat16 g_wo_hi[1048576], g_wo_lo[1048576];
__device__ __nv_bfloat16 g_q[4194304];                    // single bf16
__device__ __nv_bfloat16 g_k[4194304];                    // single bf16
__device__ __nv_bfloat16 g_v_hi[4194304], g_v_lo[4194304];
__device__ __nv_bfloat16 g_c_hi[4194304], g_c_lo[4194304];
__device__ __nv_bfloat16 g_sb[67108864];                  // scores bf16 [B*N,S,S]
__device__ __nv_bfloat16 g_p_hi[67108864], g_p_lo[67108864];

// ---------------------------------------------------------------------------
// PTX helpers
// ---------------------------------------------------------------------------
__device__ __forceinline__ uint32_t smem_u32(const void* p) {
    return (uint32_t)__cvta_generic_to_shared(p);
}
__device__ __forceinline__ void ldsm_x4(uint32_t* r, uint32_t addr) {
    asm volatile("ldmatrix.sync.aligned.m8n8.x4.shared.b16 {%0,%1,%2,%3}, [%4];"
                 : "=r"(r[0]), "=r"(r[1]), "=r"(r[2]), "=r"(r[3]) : "r"(addr));
}
__device__ __forceinline__ void ldsm_x4_t(uint32_t* r, uint32_t addr) {
    asm volatile("ldmatrix.sync.aligned.m8n8.x4.trans.shared.b16 {%0,%1,%2,%3}, [%4];"
                 : "=r"(r[0]), "=r"(r[1]), "=r"(r[2]), "=r"(r[3]) : "r"(addr));
}
__device__ __forceinline__ void mma_bf16(float* c, const uint32_t* a, const uint32_t* b) {
    asm volatile(
        "mma.sync.aligned.m16n8k16.row.col.f32.bf16.bf16.f32 "
        "{%0,%1,%2,%3}, {%4,%5,%6,%7}, {%8,%9}, {%0,%1,%2,%3};"
        : "+f"(c[0]), "+f"(c[1]), "+f"(c[2]), "+f"(c[3])
        : "r"(a[0]), "r"(a[1]), "r"(a[2]), "r"(a[3]), "r"(b[0]), "r"(b[1]));
}
__device__ __forceinline__ void split_bf16(float x, __nv_bfloat16& h, __nv_bfloat16& l) {
    h = __float2bfloat16(x);
    l = __float2bfloat16(x - __bfloat162float(h));
}
__device__ __forceinline__ void cp16(uint32_t dst, const void* src) {
    asm volatile("cp.async.cg.shared.global [%0], [%1], 16;\n" :: "r"(dst), "l"(src));
}
#define CP_COMMIT() asm volatile("cp.async.commit_group;\n")
#define CP_WAIT(n)  asm volatile("cp.async.wait_group %0;\n" :: "n"(n))

// ---------------------------------------------------------------------------
// split helpers
// ---------------------------------------------------------------------------
__device__ __forceinline__ void do_split4(float4 v, uint2* hi, uint2* lo, int i, bool wlo) {
    if (wlo) {
        __nv_bfloat16 h0, h1, h2, h3, l0, l1, l2, l3;
        split_bf16(v.x, h0, l0); split_bf16(v.y, h1, l1);
        split_bf16(v.z, h2, l2); split_bf16(v.w, h3, l3);
        __nv_bfloat162 a = __halves2bfloat162(h0, h1), b = __halves2bfloat162(h2, h3);
        __nv_bfloat162 c = __halves2bfloat162(l0, l1), d = __halves2bfloat162(l2, l3);
        hi[i] = make_uint2(*(uint32_t*)&a, *(uint32_t*)&b);
        lo[i] = make_uint2(*(uint32_t*)&c, *(uint32_t*)&d);
    } else {
        __nv_bfloat162 a = __halves2bfloat162(__float2bfloat16(v.x), __float2bfloat16(v.y));
        __nv_bfloat162 b = __halves2bfloat162(__float2bfloat16(v.z), __float2bfloat16(v.w));
        hi[i] = make_uint2(*(uint32_t*)&a, *(uint32_t*)&b);
    }
}

__global__ void split_inputs(const float4* __restrict__ from, const float4* __restrict__ to,
                             uint2* __restrict__ fh, uint2* __restrict__ th, uint2* __restrict__ tl) {
    int i = blockIdx.x * 256 + threadIdx.x;
    if (i < 1048576) {
        do_split4(from[i], fh, nullptr, i, false);
    } else {
        int j = i - 1048576;
        do_split4(to[j], th, tl, j, true);
    }
}

__global__ void split_weights(const float4* __restrict__ wq, const float4* __restrict__ wk,
                              const float4* __restrict__ wv, const float4* __restrict__ wo,
                              uint2* __restrict__ qh, uint2* __restrict__ kh,
                              uint2* __restrict__ vh, uint2* __restrict__ vl,
                              uint2* __restrict__ oh, uint2* __restrict__ ol) {
    int i = blockIdx.x * 256 + threadIdx.x;
    int sel = i >> 18, j = i & 0x3FFFF;
    if (sel == 0)      do_split4(wq[j], qh, nullptr, j, false);
    else if (sel == 1) do_split4(wk[j], kh, nullptr, j, false);
    else if (sel == 2) do_split4(wv[j], vh, vl, j, true);
    else               do_split4(wo[j], oh, ol, j, true);
}

// ---------------------------------------------------------------------------
// GEMM: C[4096,1024] = A @ W + bias, bf16 MMA, A/W pre-split.
// Block 128x128, BK=32, 8 warps (4m x 2n), 3-stage cp.async pipeline.
// MODE: 0 = fp32 out, 1 = split bf16 out, 2 = single bf16 out.
// XN:   3 = bf16x3 (hi/lo), 1 = single bf16 (hi only).
// DUAL: blockIdx.z==1 switches to the second operand set (merged Q+K proj).
// ---------------------------------------------------------------------------
template <int XN>
__device__ __forceinline__ void gemm_stage(uint32_t sb,
        const __nv_bfloat16* Ahi, const __nv_bfloat16* Alo,
        const __nv_bfloat16* Bhi, const __nv_bfloat16* Blo,
        int row0, int col0, int k0, int tid) {
    constexpr uint32_t BHI = (XN == 3) ? 10240 : 5120;
#pragma unroll
    for (int l = 0; l < 2; l++) {
        int idx = tid + l * 256;
        int m = idx >> 2, kc = (idx & 3) << 3;
        size_t so = (size_t)(row0 + m) * 1024 + k0 + kc;
        cp16(sb + (uint32_t)(m * 40 + kc) * 2, Ahi + so);
        if (XN == 3) cp16(sb + (uint32_t)(5120 + m * 40 + kc) * 2, Alo + so);
    }
#pragma unroll
    for (int l = 0; l < 2; l++) {
        int idx = tid + l * 256;
        int k = idx >> 4, nc = (idx & 15) << 3;
        size_t so = (size_t)(k0 + k) * 1024 + col0 + nc;
        cp16(sb + (uint32_t)(BHI + k * 136 + nc) * 2, Bhi + so);
        if (XN == 3) cp16(sb + (uint32_t)(14592 + k * 136 + nc) * 2, Blo + so);
    }
}

template <int MODE, int XN, bool DUAL>
__global__ __launch_bounds__(256, 2)
void gemm_bf16(const __nv_bfloat16* __restrict__ Ahi, const __nv_bfloat16* __restrict__ Alo,
               const __nv_bfloat16* __restrict__ Bhi, const __nv_bfloat16* __restrict__ Blo,
               const float* __restrict__ bias,
               float* __restrict__ Cf,
               __nv_bfloat16* __restrict__ Chi, __nv_bfloat16* __restrict__ Clo,
               const __nv_bfloat16* A2, const __nv_bfloat16* B2,
               const float* bias2, __nv_bfloat16* C2) {
    extern __shared__ __nv_bfloat16 dsm[];
    constexpr uint32_t PS  = (XN == 3) ? 18944 : 9472;
    constexpr uint32_t BHI = (XN == 3) ? 10240 : 5120;
    if (DUAL && blockIdx.z == 1) {
        Ahi = A2; Bhi = B2; bias = bias2; Chi = C2;
    }
    const int tid = threadIdx.x, lane = tid & 31, warp = tid >> 5;
    const int wm = warp >> 1, wn = warp & 1;
    const int row0 = blockIdx.y * 128, col0 = blockIdx.x * 128;
    const uint32_t sbase = smem_u32(dsm);

    float c[2][8][4];
#pragma unroll
    for (int i = 0; i < 2; i++)
#pragma unroll
        for (int j = 0; j < 8; j++)
#pragma unroll
            for (int q = 0; q < 4; q++) c[i][j][q] = 0.0f;

    gemm_stage<XN>(sbase,          Ahi, Alo, Bhi, Blo, row0, col0, 0,  tid);
    CP_COMMIT();
    gemm_stage<XN>(sbase + PS * 2, Ahi, Alo, Bhi, Blo, row0, col0, 32, tid);
    CP_COMMIT();

    const int lrow = lane & 15, koff = (lane >> 4) << 3;
    int st = 0;
    for (int k0 = 0; k0 < 1024; k0 += 32) {
        if (k0 + 32 < 1024) { CP_WAIT(1); } else { CP_WAIT(0); }
        __syncthreads();

        const uint32_t sb = sbase + (uint32_t)st * PS * 2;
#pragma unroll
        for (int ks = 0; ks < 2; ks++) {
            uint32_t ahi[2][4], alo[2][4];
#pragma unroll
            for (int mf = 0; mf < 2; mf++) {
                uint32_t off = (uint32_t)((wm * 32 + mf * 16 + lrow) * 40 + ks * 16 + koff) * 2;
                ldsm_x4(ahi[mf], sb + off);
                if (XN == 3) ldsm_x4(alo[mf], sb + 5120 * 2 + off);
            }
#pragma unroll
            for (int g = 0; g < 4; g++) {
                uint32_t bh[4], bl[4];
                uint32_t off = (uint32_t)((ks * 16 + lrow) * 136 + wn * 64 + g * 16 + koff) * 2;
                ldsm_x4_t(bh, sb + BHI * 2 + off);
                if (XN == 3) ldsm_x4_t(bl, sb + 14592 * 2 + off);
#pragma unroll
                for (int h = 0; h < 2; h++) {
                    int nf = g * 2 + h;
#pragma unroll
                    for (int mf = 0; mf < 2; mf++) {
                        mma_bf16(c[mf][nf], ahi[mf], bh + h * 2);
                        if (XN == 3) {
                            mma_bf16(c[mf][nf], ahi[mf], bl + h * 2);
                            mma_bf16(c[mf][nf], alo[mf], bh + h * 2);
                        }
                    }
                }
            }
        }
        if (k0 + 64 < 1024) {
            int nst = (st + 2 > 2) ? (st - 1) : (st + 2);
            gemm_stage<XN>(sbase + (uint32_t)nst * PS * 2, Ahi, Alo, Bhi, Blo,
                           row0, col0, k0 + 64, tid);
            CP_COMMIT();
        }
        st = (st == 2) ? 0 : st + 1;
    }

    const int rbase = row0 + wm * 32 + (lane >> 2);
    const int cbase = col0 + wn * 64 + (lane & 3) * 2;
#pragma unroll
    for (int mf = 0; mf < 2; mf++) {
#pragma unroll
        for (int nf = 0; nf < 8; nf++) {
            int r = rbase + mf * 16;
            int cc = cbase + nf * 8;
            float2 bv = *(const float2*)(bias + cc);
            float v00 = c[mf][nf][0] + bv.x, v01 = c[mf][nf][1] + bv.y;
            float v10 = c[mf][nf][2] + bv.x, v11 = c[mf][nf][3] + bv.y;
            if (MODE == 1) {
                __nv_bfloat16 h0, l0, h1, l1;
                split_bf16(v00, h0, l0); split_bf16(v01, h1, l1);
                *(__nv_bfloat162*)(Chi + (size_t)r * 1024 + cc) = __halves2bfloat162(h0, h1);
                *(__nv_bfloat162*)(Clo + (size_t)r * 1024 + cc) = __halves2bfloat162(l0, l1);
                split_bf16(v10, h0, l0); split_bf16(v11, h1, l1);
                *(__nv_bfloat162*)(Chi + (size_t)(r + 8) * 1024 + cc) = __halves2bfloat162(h0, h1);
                *(__nv_bfloat162*)(Clo + (size_t)(r + 8) * 1024 + cc) = __halves2bfloat162(l0, l1);
            } else if (MODE == 2) {
                *(__nv_bfloat162*)(Chi + (size_t)r * 1024 + cc) =
                    __halves2bfloat162(__float2bfloat16(v00), __float2bfloat16(v01));
                *(__nv_bfloat162*)(Chi + (size_t)(r + 8) * 1024 + cc) =
                    __halves2bfloat162(__float2bfloat16(v10), __float2bfloat16(v11));
            } else {
                *(float2*)(Cf + (size_t)r * 1024 + cc)       = make_float2(v00, v01);
                *(float2*)(Cf + (size_t)(r + 8) * 1024 + cc) = make_float2(v10, v11);
            }
        }
    }
}

// ---------------------------------------------------------------------------
// qk: scores[z,f,t] = 0.125 * sum_h q[..f,n,h] * k[..t,n,h], SINGLE bf16 MMA.
// ---------------------------------------------------------------------------
__global__ __launch_bounds__(256)
void qk_mma() {
    extern __shared__ __nv_bfloat16 dsm[];
    const int tid = threadIdx.x, lane = tid & 31, warp = tid >> 5;
    const int wm = warp >> 1, wn = warp & 1;
    const int z = blockIdx.z, b = z >> 4, n = z & 15;
    const int t0 = blockIdx.x * 128, f0 = blockIdx.y * 128;
    const uint32_t sbase = smem_u32(dsm);

    const size_t qoff = ((size_t)(b * 1024 + f0) * 16 + n) * 64;
    const size_t koffg = ((size_t)(b * 1024 + t0) * 16 + n) * 64;

#pragma unroll
    for (int l = 0; l < 4; l++) {
        int idx = tid + l * 256;
        int m = idx >> 3, hc = (idx & 7) << 3;
        size_t so = (size_t)m * 1024 + hc;
        uint32_t doff = (uint32_t)(m * 72 + hc) * 2;
        cp16(sbase + doff,            g_q + qoff + so);
        cp16(sbase + 9216 * 2 + doff, g_k + koffg + so);
    }
    CP_COMMIT();
    CP_WAIT(0);
    __syncthreads();

    float c[2][8][4];
#pragma unroll
    for (int i = 0; i < 2; i++)
#pragma unroll
        for (int j = 0; j < 8; j++)
#pragma unroll
            for (int q = 0; q < 4; q++) c[i][j][q] = 0.0f;

    const int lrow = lane & 15, koff = (lane >> 4) << 3;
#pragma unroll
    for (int ks = 0; ks < 4; ks++) {
        uint32_t a[2][4];
#pragma unroll
        for (int mf = 0; mf < 2; mf++) {
            uint32_t off = (uint32_t)((wm * 32 + mf * 16 + lrow) * 72 + ks * 16 + koff) * 2;
            ldsm_x4(a[mf], sbase + off);
        }
#pragma unroll
        for (int g = 0; g < 4; g++) {
            uint32_t rh[4];
            uint32_t off = (uint32_t)((wn * 64 + g * 16 + lrow) * 72 + ks * 16 + koff) * 2;
            ldsm_x4(rh, sbase + 9216 * 2 + off);
            uint32_t b0[2] = {rh[0], rh[2]}, b1[2] = {rh[1], rh[3]};
#pragma unroll
            for (int mf = 0; mf < 2; mf++) {
                mma_bf16(c[mf][g * 2 + 0], a[mf], b0);
                mma_bf16(c[mf][g * 2 + 1], a[mf], b1);
            }
        }
    }

    __nv_bfloat16* out = g_sb + (size_t)z * 1048576;
    const int rbase = f0 + wm * 32 + (lane >> 2);
    const int cbase = t0 + wn * 64 + (lane & 3) * 2;
#pragma unroll
    for (int mf = 0; mf < 2; mf++) {
#pragma unroll
        for (int nf = 0; nf < 8; nf++) {
            int r = rbase + mf * 16, cc = cbase + nf * 8;
            *(__nv_bfloat162*)(out + (size_t)r * 1024 + cc) =
                __halves2bfloat162(__float2bfloat16(c[mf][nf][0] * 0.125f),
                                   __float2bfloat16(c[mf][nf][1] * 0.125f));
            *(__nv_bfloat162*)(out + (size_t)(r + 8) * 1024 + cc) =
                __halves2bfloat162(__float2bfloat16(c[mf][nf][2] * 0.125f),
                                   __float2bfloat16(c[mf][nf][3] * 0.125f));
        }
    }
}

// ---------------------------------------------------------------------------
// fused premix(MMA) -> mask -> softmax -> postmix(FFMA).  (round-8 version:
// 102912 B dyn smem -> 2 CTAs/SM.)
// smem: sbf bf16[16][1032] (33024B) | s f32[16][1028] (65792B) | smadd[1024] (4096B)
// ---------------------------------------------------------------------------
#define SW 1028
#define SBFS 1032
__global__ __launch_bounds__(256)
void mix_softmax_kernel(const int* __restrict__ amask,
                        const float* __restrict__ pre,
                        const float* __restrict__ post) {
    extern __shared__ char dynsm[];
    __nv_bfloat16* sbf = (__nv_bfloat16*)dynsm;
    float* s     = (float*)(dynsm + 33024);
    float* smadd = (float*)(dynsm + 33024 + 65792);
    __shared__ float wpre[256], wpost[256], sinv[16];
    const int tid = threadIdx.x, lane = tid & 31, warp = tid >> 5;
    const int f = blockIdx.x, b = blockIdx.y;

    wpre[tid]  = pre[tid];
    wpost[tid] = post[tid];

    const size_t rowbase = ((size_t)(b * 16) * 1024 + f) * 1024;
    const uint32_t sbf_u32 = smem_u32(sbf);

#pragma unroll
    for (int l = 0; l < 8; l++) {
        int idx = tid + l * 256;
        int n = idx >> 7, ch = idx & 127;
        cp16(sbf_u32 + (uint32_t)(n * SBFS + ch * 8) * 2,
             g_sb + rowbase + (size_t)n * 1048576 + ch * 8);
    }
    CP_COMMIT();

    {
        int4 mv = *(const int4*)(amask + ((size_t)b * 1024 + f) * 1024 + tid * 4);
        smadd[tid * 4 + 0] = (1.0f - (float)mv.x) * -10000.0f;
        smadd[tid * 4 + 1] = (1.0f - (float)mv.y) * -10000.0f;
        smadd[tid * 4 + 2] = (1.0f - (float)mv.z) * -10000.0f;
        smadd[tid * 4 + 3] = (1.0f - (float)mv.w) * -10000.0f;
    }
    CP_WAIT(0);
    __syncthreads();

    // premix via MMA
    {
        const int g = lane >> 2, t4 = lane & 3;
        uint32_t awh[4], awl[4];
#pragma unroll
        for (int q = 0; q < 4; q++) {
            int kk = 2 * t4 + (q >> 1) * 8;
            int rr = g + (q & 1) * 8;
            __nv_bfloat16 h0, l0, h1, l1;
            split_bf16(wpre[kk * 16 + rr], h0, l0);
            split_bf16(wpre[(kk + 1) * 16 + rr], h1, l1);
            __nv_bfloat162 ph = __halves2bfloat162(h0, h1), pl = __halves2bfloat162(l0, l1);
            awh[q] = *(uint32_t*)&ph;
            awl[q] = *(uint32_t*)&pl;
        }
        const int t0 = warp * 128;
#pragma unroll
        for (int blk = 0; blk < 8; blk++) {
            int tb = t0 + blk * 16;
            uint32_t bfr[4];
            ldsm_x4_t(bfr, sbf_u32 + (uint32_t)((lane & 15) * SBFS + tb + ((lane >> 4) << 3)) * 2);
#pragma unroll
            for (int h = 0; h < 2; h++) {
                int cb = tb + h * 8 + 2 * t4;
                float m0 = smadd[cb], m1 = smadd[cb + 1];
                float c[4] = {m0, m1, m0, m1};
                mma_bf16(c, awh, bfr + h * 2);
                mma_bf16(c, awl, bfr + h * 2);
                *(float2*)&s[g * SW + cb]       = make_float2(c[0], c[1]);
                *(float2*)&s[(g + 8) * SW + cb] = make_float2(c[2], c[3]);
            }
        }
    }
    __syncthreads();

    // softmax
#pragma unroll
    for (int r = 0; r < 2; r++) {
        int l = warp * 2 + r;
        float m = -1e30f;
        for (int it = lane; it < 1024; it += 32) m = fmaxf(m, s[l * SW + it]);
#pragma unroll
        for (int o = 16; o > 0; o >>= 1) m = fmaxf(m, __shfl_xor_sync(0xffffffffu, m, o));
        float sum = 0.0f;
        for (int it = lane; it < 1024; it += 32) {
            float e = __expf(s[l * SW + it] - m);
            s[l * SW + it] = e;
            sum += e;
        }
#pragma unroll
        for (int o = 16; o > 0; o >>= 1) sum += __shfl_xor_sync(0xffffffffu, sum, o);
        if (lane == 0) sinv[l] = 1.0f / sum;
    }
    __syncthreads();

    // postmix (scalar FFMA), write split-bf16 P
#pragma unroll
    for (int c = 0; c < 2; c++) {
        int t = (tid + c * 256) * 2;
        float x0[16], x1[16];
#pragma unroll
        for (int n = 0; n < 16; n++) {
            x0[n] = s[n * SW + t] * sinv[n];
            x1[n] = s[n * SW + t + 1] * sinv[n];
        }
#pragma unroll
        for (int l = 0; l < 16; l++) {
            float y0 = 0.0f, y1 = 0.0f;
#pragma unroll
            for (int n = 0; n < 16; n++) {
                y0 = fmaf(x0[n], wpost[n * 16 + l], y0);
                y1 = fmaf(x1[n], wpost[n * 16 + l], y1);
            }
            __nv_bfloat16 h0, l0, h1, l1;
            split_bf16(y0, h0, l0); split_bf16(y1, h1, l1);
            size_t base = rowbase + (size_t)l * 1048576 + t;
            *(__nv_bfloat162*)(g_p_hi + base) = __halves2bfloat162(h0, h1);
            *(__nv_bfloat162*)(g_p_lo + base) = __halves2bfloat162(l0, l1);
        }
    }
}

// ---------------------------------------------------------------------------
// pv: ctx[b,f,n,h] = sum_t P[z,f,t] * v[b,t,n,h], bf16x3 MMA (P,V split).
// Block = 128f x 64h, BK=32, 3-stage cp.async.  (round-10 version)
// ---------------------------------------------------------------------------
#define PV_PS 14848
__device__ __forceinline__ void pv_stage(uint32_t sb, size_t pbase, size_t vbase,
                                         int k0, int tid) {
#pragma unroll
    for (int l = 0; l < 2; l++) {
        int idx = tid + l * 256;
        int m = idx >> 2, tc = (idx & 3) << 3;
        size_t so = pbase + (size_t)m * 1024 + k0 + tc;
        cp16(sb + (uint32_t)(m * 40 + tc) * 2, g_p_hi + so);
        cp16(sb + (uint32_t)(5120 + m * 40 + tc) * 2, g_p_lo + so);
    }
    {
        int tr = tid >> 3, hc = (tid & 7) << 3;
        size_t so = vbase + (size_t)(k0 + tr) * 1024 + hc;
        cp16(sb + (uint32_t)(10240 + tr * 72 + hc) * 2, g_v_hi + so);
        cp16(sb + (uint32_t)(12544 + tr * 72 + hc) * 2, g_v_lo + so);
    }
}

__global__ __launch_bounds__(256)
void pv_mma() {
    extern __shared__ __nv_bfloat16 dsm[];
    const int tid = threadIdx.x, lane = tid & 31, warp = tid >> 5;
    const int wm = warp >> 1, wn = warp & 1;
    const int z = blockIdx.y, b = z >> 4, n = z & 15;
    const int f0 = blockIdx.x * 128;
    const uint32_t sbase = smem_u32(dsm);

    const size_t pbase = (size_t)z * 1048576 + (size_t)f0 * 1024;
    const size_t vbase = (size_t)(b * 1024) * 1024 + (size_t)n * 64;

    float c[2][4][4];
#pragma unroll
    for (int i = 0; i < 2; i++)
#pragma unroll
        for (int j = 0; j < 4; j++)
#pragma unroll
            for (int q = 0; q < 4; q++) c[i][j][q] = 0.0f;

    pv_stage(sbase,              pbase, vbase, 0,  tid);
    CP_COMMIT();
    pv_stage(sbase + PV_PS * 2,  pbase, vbase, 32, tid);
    CP_COMMIT();

    const int lrow = lane & 15, koff = (lane >> 4) << 3;
    int st = 0;
    for (int k0 = 0; k0 < 1024; k0 += 32) {
        if (k0 + 32 < 1024) { CP_WAIT(1); } else { CP_WAIT(0); }
        __syncthreads();

        const uint32_t sb = sbase + (uint32_t)st * PV_PS * 2;
#pragma unroll
        for (int ks = 0; ks < 2; ks++) {
            uint32_t ahi[2][4], alo[2][4];
#pragma unroll
            for (int mf = 0; mf < 2; mf++) {
                uint32_t off = (uint32_t)((wm * 32 + mf * 16 + lrow) * 40 + ks * 16 + koff) * 2;
                ldsm_x4(ahi[mf], sb + off);
                ldsm_x4(alo[mf], sb + 5120 * 2 + off);
            }
#pragma unroll
            for (int g = 0; g < 2; g++) {
                uint32_t bh[4], bl[4];
                uint32_t off = (uint32_t)((ks * 16 + lrow) * 72 + wn * 32 + g * 16 + koff) * 2;
                ldsm_x4_t(bh, sb + 10240 * 2 + off);
                ldsm_x4_t(bl, sb + 12544 * 2 + off);
#pragma unroll
                for (int h = 0; h < 2; h++) {
                    int nf = g * 2 + h;
#pragma unroll
                    for (int mf = 0; mf < 2; mf++) {
                        mma_bf16(c[mf][nf], ahi[mf], bh + h * 2);
                        mma_bf16(c[mf][nf], ahi[mf], bl + h * 2);
                        mma_bf16(c[mf][nf], alo[mf], bh + h * 2);
                    }
                }
            }
        }
        if (k0 + 64 < 1024) {
            int nst = (st + 2 > 2) ? (st - 1) : (st + 2);
            pv_stage(sbase + (uint32_t)nst * PV_PS * 2, pbase, vbase, k0 + 64, tid);
            CP_COMMIT();
        }
        st = (st == 2) ? 0 : st + 1;
    }

    const int rbase = f0 + wm * 32 + (lane >> 2);
    const int cbase = wn * 32 + (lane & 3) * 2;
#pragma unroll
    for (int mf = 0; mf < 2; mf++) {
#pragma unroll
        for (int nf = 0; nf < 4; nf++) {
            int r = rbase + mf * 16, cc = cbase + nf * 8;
            size_t o0 = ((size_t)(b * 1024 + r) * 16 + n) * 64 + cc;
            size_t o1 = ((size_t)(b * 1024 + r + 8) * 16 + n) * 64 + cc;
            __nv_bfloat16 h0, l0, h1, l1;
            split_bf16(c[mf][nf][0], h0, l0); split_bf16(c[mf][nf][1], h1, l1);
            *(__nv_bfloat162*)(g_c_hi + o0) = __halves2bfloat162(h0, h1);
            *(__nv_bfloat162*)(g_c_lo + o0) = __halves2bfloat162(l0, l1);
            split_bf16(c[mf][nf][2], h0, l0); split_bf16(c[mf][nf][3], h1, l1);
            *(__nv_bfloat162*)(g_c_hi + o1) = __halves2bfloat162(h0, h1);
            *(__nv_bfloat162*)(g_c_lo + o1) = __halves2bfloat162(l0, l1);
        }
    }
}

// ---------------------------------------------------------------------------
extern "C" void kernel_launch(void* const* d_in, const int* in_sizes, int n_in,
                              void* d_out, int out_size) {
    const float* from  = (const float*)d_in[0];
    const float* to    = (const float*)d_in[1];
    const int*   amask = (const int*)d_in[2];
    const float* wq    = (const float*)d_in[3];
    const float* bq    = (const float*)d_in[4];
    const float* wk    = (const float*)d_in[5];
    const float* bk    = (const float*)d_in[6];
    const float* wv    = (const float*)d_in[7];
    const float* bv    = (const float*)d_in[8];
    const float* pre   = (const float*)d_in[9];
    const float* post  = (const float*)d_in[10];
    const float* wo    = (const float*)d_in[11];
    const float* bo    = (const float*)d_in[12];
    float* out = (float*)d_out;

    void *fh, *th, *tl, *qwh, *kwh, *vwh, *vwl, *owh, *owl;
    void *qp, *kp, *vh, *vl, *ch, *cl;
    cudaGetSymbolAddress(&fh, g_from_hi);
    cudaGetSymbolAddress(&th, g_to_hi);   cudaGetSymbolAddress(&tl, g_to_lo);
    cudaGetSymbolAddress(&qwh, g_wq_hi);
    cudaGetSymbolAddress(&kwh, g_wk_hi);
    cudaGetSymbolAddress(&vwh, g_wv_hi);  cudaGetSymbolAddress(&vwl, g_wv_lo);
    cudaGetSymbolAddress(&owh, g_wo_hi);  cudaGetSymbolAddress(&owl, g_wo_lo);
    cudaGetSymbolAddress(&qp, g_q);       cudaGetSymbolAddress(&kp, g_k);
    cudaGetSymbolAddress(&vh, g_v_hi);    cudaGetSymbolAddress(&vl, g_v_lo);
    cudaGetSymbolAddress(&ch, g_c_hi);    cudaGetSymbolAddress(&cl, g_c_lo);

    const int GEMM3_SMEM = 3 * 18944 * 2;     // 113664 B
    const int GEMM1_SMEM = 3 * 9472 * 2;      // 56832 B
    const int QK_SMEM    = 18432 * 2;         // 36864 B
    const int PV_SMEM    = 3 * PV_PS * 2;     // 89088 B
    const int SMX_SMEM   = 33024 + 65792 + 4096;  // 102912 B -> 2 CTAs/SM
    cudaFuncSetAttribute((const void*)gemm_bf16<0, 3, false>, cudaFuncAttributeMaxDynamicSharedMemorySize, GEMM3_SMEM);
    cudaFuncSetAttribute((const void*)gemm_bf16<1, 3, false>, cudaFuncAttributeMaxDynamicSharedMemorySize, GEMM3_SMEM);
    cudaFuncSetAttribute((const void*)gemm_bf16<2, 1, true>,  cudaFuncAttributeMaxDynamicSharedMemorySize, GEMM1_SMEM);
    cudaFuncSetAttribute((const void*)qk_mma,                 cudaFuncAttributeMaxDynamicSharedMemorySize, QK_SMEM);
    cudaFuncSetAttribute((const void*)pv_mma,                 cudaFuncAttributeMaxDynamicSharedMemorySize, PV_SMEM);
    cudaFuncSetAttribute((const void*)mix_softmax_kernel,     cudaFuncAttributeMaxDynamicSharedMemorySize, SMX_SMEM);

    // side stream + fork/join events (created once on the first, uncaptured,
    // correctness call; no device memory involved; identical work every call)
    static cudaStream_t s2 = nullptr;
    static cudaEvent_t evFork = nullptr, evJoin = nullptr;
    if (s2 == nullptr) {
        cudaStreamCreateWithFlags(&s2, cudaStreamNonBlocking);
        cudaEventCreateWithFlags(&evFork, cudaEventDisableTiming);
        cudaEventCreateWithFlags(&evJoin, cudaEventDisableTiming);
    }

    split_inputs<<<8192, 256>>>((const float4*)from, (const float4*)to,
                                (uint2*)fh, (uint2*)th, (uint2*)tl);
    split_weights<<<4096, 256>>>((const float4*)wq, (const float4*)wk,
                                 (const float4*)wv, (const float4*)wo,
                                 (uint2*)qwh, (uint2*)kwh,
                                 (uint2*)vwh, (uint2*)vwl,
                                 (uint2*)owh, (uint2*)owl);

    // fork: V projection runs on s2, concurrent with QK-proj -> qk -> softmax
    cudaEventRecord(evFork, 0);
    cudaStreamWaitEvent(s2, evFork, 0);
    gemm_bf16<1, 3, false><<<dim3(8, 32), 256, GEMM3_SMEM, s2>>>(
        (const __nv_bfloat16*)th, (const __nv_bfloat16*)tl,
        (const __nv_bfloat16*)vwh, (const __nv_bfloat16*)vwl, bv,
        nullptr, (__nv_bfloat16*)vh, (__nv_bfloat16*)vl,
        nullptr, nullptr, nullptr, nullptr);
    cudaEventRecord(evJoin, s2);

    // merged Q+K projections (z=0 -> Q, z=1 -> K), single bf16
    gemm_bf16<2, 1, true><<<dim3(8, 32, 2), 256, GEMM1_SMEM>>>(
        (const __nv_bfloat16*)fh, nullptr,
        (const __nv_bfloat16*)qwh, nullptr, bq,
        nullptr, (__nv_bfloat16*)qp, nullptr,
        (const __nv_bfloat16*)th, (const __nv_bfloat16*)kwh, bk, (__nv_bfloat16*)kp);

    qk_mma<<<dim3(8, 8, 64), 256, QK_SMEM>>>();

    mix_softmax_kernel<<<dim3(1024, 4), 256, SMX_SMEM>>>(amask, pre, post);

    // join: pv needs V from s2
    cudaStreamWaitEvent((cudaStream_t)0, evJoin, 0);

    pv_mma<<<dim3(8, 64), 256, PV_SMEM>>>();

    // out projection: full bf16x3
    gemm_bf16<0, 3, false><<<dim3(8, 32), 256, GEMM3_SMEM>>>(
        (const __nv_bfloat16*)ch, (const __nv_bfloat16*)cl,
        (const __nv_bfloat16*)owh, (const __nv_bfloat16*)owl, bo,
        out, nullptr, nullptr,
        nullptr, nullptr, nullptr, nullptr);
}

// round 13
// speedup vs baseline: 1.1049x; 1.0119x over previous
#include <cuda_runtime.h>
#include <cuda_bf16.h>
#include <cstdint>
#include <cstddef>

typedef unsigned long long ull;

// ---------------- scratch (device globals: no cudaMalloc allowed) ----------
__device__ __nv_bfloat16 g_from_hi[4194304];
__device__ __nv_bfloat16 g_to_hi[4194304], g_to_lo[4194304];
__device__ __nv_bfloat16 g_wq_hi[1048576];
__device__ __nv_bfloat16 g_wk_hi[1048576];
__device__ __nv_bfloat16 g_wv_hi[1048576], g_wv_lo[1048576];
__device__ __nv_bfloat16 g_wo_hi[1048576], g_wo_lo[1048576];
__device__ __nv_bfloat16 g_q[4194304];                    // single bf16
__device__ __nv_bfloat16 g_k[4194304];                    // single bf16
__device__ __nv_bfloat16 g_v_hi[4194304], g_v_lo[4194304];
__device__ __nv_bfloat16 g_c_hi[4194304], g_c_lo[4194304];
__device__ __nv_bfloat16 g_sb[67108864];                  // scores bf16 [B*N,S,S]
__device__ __nv_bfloat16 g_p_hi[67108864], g_p_lo[67108864];

// ---------------------------------------------------------------------------
// PTX helpers
// ---------------------------------------------------------------------------
__device__ __forceinline__ uint32_t smem_u32(const void* p) {
    return (uint32_t)__cvta_generic_to_shared(p);
}
__device__ __forceinline__ void ldsm_x4(uint32_t* r, uint32_t addr) {
    asm volatile("ldmatrix.sync.aligned.m8n8.x4.shared.b16 {%0,%1,%2,%3}, [%4];"
                 : "=r"(r[0]), "=r"(r[1]), "=r"(r[2]), "=r"(r[3]) : "r"(addr));
}
__device__ __forceinline__ void ldsm_x4_t(uint32_t* r, uint32_t addr) {
    asm volatile("ldmatrix.sync.aligned.m8n8.x4.trans.shared.b16 {%0,%1,%2,%3}, [%4];"
                 : "=r"(r[0]), "=r"(r[1]), "=r"(r[2]), "=r"(r[3]) : "r"(addr));
}
__device__ __forceinline__ void mma_bf16(float* c, const uint32_t* a, const uint32_t* b) {
    asm volatile(
        "mma.sync.aligned.m16n8k16.row.col.f32.bf16.bf16.f32 "
        "{%0,%1,%2,%3}, {%4,%5,%6,%7}, {%8,%9}, {%0,%1,%2,%3};"
        : "+f"(c[0]), "+f"(c[1]), "+f"(c[2]), "+f"(c[3])
        : "r"(a[0]), "r"(a[1]), "r"(a[2]), "r"(a[3]), "r"(b[0]), "r"(b[1]));
}
__device__ __forceinline__ void split_bf16(float x, __nv_bfloat16& h, __nv_bfloat16& l) {
    h = __float2bfloat16(x);
    l = __float2bfloat16(x - __bfloat162float(h));
}
__device__ __forceinline__ void cp16(uint32_t dst, const void* src) {
    asm volatile("cp.async.cg.shared.global [%0], [%1], 16;\n" :: "r"(dst), "l"(src));
}
#define CP_COMMIT() asm volatile("cp.async.commit_group;\n")
#define CP_WAIT(n)  asm volatile("cp.async.wait_group %0;\n" :: "n"(n))

// ---------------------------------------------------------------------------
// split helpers
// ---------------------------------------------------------------------------
__device__ __forceinline__ void do_split4(float4 v, uint2* hi, uint2* lo, int i, bool wlo) {
    if (wlo) {
        __nv_bfloat16 h0, h1, h2, h3, l0, l1, l2, l3;
        split_bf16(v.x, h0, l0); split_bf16(v.y, h1, l1);
        split_bf16(v.z, h2, l2); split_bf16(v.w, h3, l3);
        __nv_bfloat162 a = __halves2bfloat162(h0, h1), b = __halves2bfloat162(h2, h3);
        __nv_bfloat162 c = __halves2bfloat162(l0, l1), d = __halves2bfloat162(l2, l3);
        hi[i] = make_uint2(*(uint32_t*)&a, *(uint32_t*)&b);
        lo[i] = make_uint2(*(uint32_t*)&c, *(uint32_t*)&d);
    } else {
        __nv_bfloat162 a = __halves2bfloat162(__float2bfloat16(v.x), __float2bfloat16(v.y));
        __nv_bfloat162 b = __halves2bfloat162(__float2bfloat16(v.z), __float2bfloat16(v.w));
        hi[i] = make_uint2(*(uint32_t*)&a, *(uint32_t*)&b);
    }
}

__global__ void split_inputs(const float4* __restrict__ from, const float4* __restrict__ to,
                             uint2* __restrict__ fh, uint2* __restrict__ th, uint2* __restrict__ tl) {
    int i = blockIdx.x * 256 + threadIdx.x;
    if (i < 1048576) {
        do_split4(from[i], fh, nullptr, i, false);
    } else {
        int j = i - 1048576;
        do_split4(to[j], th, tl, j, true);
    }
}

__global__ void split_weights(const float4* __restrict__ wq, const float4* __restrict__ wk,
                              const float4* __restrict__ wv, const float4* __restrict__ wo,
                              uint2* __restrict__ qh, uint2* __restrict__ kh,
                              uint2* __restrict__ vh, uint2* __restrict__ vl,
                              uint2* __restrict__ oh, uint2* __restrict__ ol) {
    int i = blockIdx.x * 256 + threadIdx.x;
    int sel = i >> 18, j = i & 0x3FFFF;
    if (sel == 0)      do_split4(wq[j], qh, nullptr, j, false);
    else if (sel == 1) do_split4(wk[j], kh, nullptr, j, false);
    else if (sel == 2) do_split4(wv[j], vh, vl, j, true);
    else               do_split4(wo[j], oh, ol, j, true);
}

// ---------------------------------------------------------------------------
// GEMM: C = A @ W + bias, bf16 MMA, A/W pre-split.
// Block 128x128, BK=32, 8 warps (4m x 2n), 3-stage cp.async pipeline.
// MODE: 0 = fp32 out, 1 = split bf16 out, 2 = single bf16 out.
// XN:   3 = bf16x3 (hi/lo), 1 = single bf16 (hi only).
// DUAL: blockIdx.z==1 switches to the second operand set (merged Q+K proj).
// ---------------------------------------------------------------------------
template <int XN>
__device__ __forceinline__ void gemm_stage(uint32_t sb,
        const __nv_bfloat16* Ahi, const __nv_bfloat16* Alo,
        const __nv_bfloat16* Bhi, const __nv_bfloat16* Blo,
        int row0, int col0, int k0, int tid) {
    constexpr uint32_t BHI = (XN == 3) ? 10240 : 5120;
#pragma unroll
    for (int l = 0; l < 2; l++) {
        int idx = tid + l * 256;
        int m = idx >> 2, kc = (idx & 3) << 3;
        size_t so = (size_t)(row0 + m) * 1024 + k0 + kc;
        cp16(sb + (uint32_t)(m * 40 + kc) * 2, Ahi + so);
        if (XN == 3) cp16(sb + (uint32_t)(5120 + m * 40 + kc) * 2, Alo + so);
    }
#pragma unroll
    for (int l = 0; l < 2; l++) {
        int idx = tid + l * 256;
        int k = idx >> 4, nc = (idx & 15) << 3;
        size_t so = (size_t)(k0 + k) * 1024 + col0 + nc;
        cp16(sb + (uint32_t)(BHI + k * 136 + nc) * 2, Bhi + so);
        if (XN == 3) cp16(sb + (uint32_t)(14592 + k * 136 + nc) * 2, Blo + so);
    }
}

template <int MODE, int XN, bool DUAL>
__global__ __launch_bounds__(256, 2)
void gemm_bf16(const __nv_bfloat16* __restrict__ Ahi, const __nv_bfloat16* __restrict__ Alo,
               const __nv_bfloat16* __restrict__ Bhi, const __nv_bfloat16* __restrict__ Blo,
               const float* __restrict__ bias,
               float* __restrict__ Cf,
               __nv_bfloat16* __restrict__ Chi, __nv_bfloat16* __restrict__ Clo,
               const __nv_bfloat16* A2, const __nv_bfloat16* B2,
               const float* bias2, __nv_bfloat16* C2) {
    extern __shared__ __nv_bfloat16 dsm[];
    constexpr uint32_t PS  = (XN == 3) ? 18944 : 9472;
    constexpr uint32_t BHI = (XN == 3) ? 10240 : 5120;
    if (DUAL && blockIdx.z == 1) {
        Ahi = A2; Bhi = B2; bias = bias2; Chi = C2;
    }
    const int tid = threadIdx.x, lane = tid & 31, warp = tid >> 5;
    const int wm = warp >> 1, wn = warp & 1;
    const int row0 = blockIdx.y * 128, col0 = blockIdx.x * 128;
    const uint32_t sbase = smem_u32(dsm);

    float c[2][8][4];
#pragma unroll
    for (int i = 0; i < 2; i++)
#pragma unroll
        for (int j = 0; j < 8; j++)
#pragma unroll
            for (int q = 0; q < 4; q++) c[i][j][q] = 0.0f;

    gemm_stage<XN>(sbase,          Ahi, Alo, Bhi, Blo, row0, col0, 0,  tid);
    CP_COMMIT();
    gemm_stage<XN>(sbase + PS * 2, Ahi, Alo, Bhi, Blo, row0, col0, 32, tid);
    CP_COMMIT();

    const int lrow = lane & 15, koff = (lane >> 4) << 3;
    int st = 0;
    for (int k0 = 0; k0 < 1024; k0 += 32) {
        if (k0 + 32 < 1024) { CP_WAIT(1); } else { CP_WAIT(0); }
        __syncthreads();

        const uint32_t sb = sbase + (uint32_t)st * PS * 2;
#pragma unroll
        for (int ks = 0; ks < 2; ks++) {
            uint32_t ahi[2][4], alo[2][4];
#pragma unroll
            for (int mf = 0; mf < 2; mf++) {
                uint32_t off = (uint32_t)((wm * 32 + mf * 16 + lrow) * 40 + ks * 16 + koff) * 2;
                ldsm_x4(ahi[mf], sb + off);
                if (XN == 3) ldsm_x4(alo[mf], sb + 5120 * 2 + off);
            }
#pragma unroll
            for (int g = 0; g < 4; g++) {
                uint32_t bh[4], bl[4];
                uint32_t off = (uint32_t)((ks * 16 + lrow) * 136 + wn * 64 + g * 16 + koff) * 2;
                ldsm_x4_t(bh, sb + BHI * 2 + off);
                if (XN == 3) ldsm_x4_t(bl, sb + 14592 * 2 + off);
#pragma unroll
                for (int h = 0; h < 2; h++) {
                    int nf = g * 2 + h;
#pragma unroll
                    for (int mf = 0; mf < 2; mf++) {
                        mma_bf16(c[mf][nf], ahi[mf], bh + h * 2);
                        if (XN == 3) {
                            mma_bf16(c[mf][nf], ahi[mf], bl + h * 2);
                            mma_bf16(c[mf][nf], alo[mf], bh + h * 2);
                        }
                    }
                }
            }
        }
        if (k0 + 64 < 1024) {
            int nst = (st + 2 > 2) ? (st - 1) : (st + 2);
            gemm_stage<XN>(sbase + (uint32_t)nst * PS * 2, Ahi, Alo, Bhi, Blo,
                           row0, col0, k0 + 64, tid);
            CP_COMMIT();
        }
        st = (st == 2) ? 0 : st + 1;
    }

    const int rbase = row0 + wm * 32 + (lane >> 2);
    const int cbase = col0 + wn * 64 + (lane & 3) * 2;
#pragma unroll
    for (int mf = 0; mf < 2; mf++) {
#pragma unroll
        for (int nf = 0; nf < 8; nf++) {
            int r = rbase + mf * 16;
            int cc = cbase + nf * 8;
            float2 bv = *(const float2*)(bias + cc);
            float v00 = c[mf][nf][0] + bv.x, v01 = c[mf][nf][1] + bv.y;
            float v10 = c[mf][nf][2] + bv.x, v11 = c[mf][nf][3] + bv.y;
            if (MODE == 1) {
                __nv_bfloat16 h0, l0, h1, l1;
                split_bf16(v00, h0, l0); split_bf16(v01, h1, l1);
                *(__nv_bfloat162*)(Chi + (size_t)r * 1024 + cc) = __halves2bfloat162(h0, h1);
                *(__nv_bfloat162*)(Clo + (size_t)r * 1024 + cc) = __halves2bfloat162(l0, l1);
                split_bf16(v10, h0, l0); split_bf16(v11, h1, l1);
                *(__nv_bfloat162*)(Chi + (size_t)(r + 8) * 1024 + cc) = __halves2bfloat162(h0, h1);
                *(__nv_bfloat162*)(Clo + (size_t)(r + 8) * 1024 + cc) = __halves2bfloat162(l0, l1);
            } else if (MODE == 2) {
                *(__nv_bfloat162*)(Chi + (size_t)r * 1024 + cc) =
                    __halves2bfloat162(__float2bfloat16(v00), __float2bfloat16(v01));
                *(__nv_bfloat162*)(Chi + (size_t)(r + 8) * 1024 + cc) =
                    __halves2bfloat162(__float2bfloat16(v10), __float2bfloat16(v11));
            } else {
                *(float2*)(Cf + (size_t)r * 1024 + cc)       = make_float2(v00, v01);
                *(float2*)(Cf + (size_t)(r + 8) * 1024 + cc) = make_float2(v10, v11);
            }
        }
    }
}

// ---------------------------------------------------------------------------
// qk: scores[z,f,t] = 0.125 * sum_h q * k, SINGLE bf16 MMA.  zbase = b0*16.
// ---------------------------------------------------------------------------
__global__ __launch_bounds__(256)
void qk_mma(int zbase) {
    extern __shared__ __nv_bfloat16 dsm[];
    const int tid = threadIdx.x, lane = tid & 31, warp = tid >> 5;
    const int wm = warp >> 1, wn = warp & 1;
    const int z = blockIdx.z + zbase, b = z >> 4, n = z & 15;
    const int t0 = blockIdx.x * 128, f0 = blockIdx.y * 128;
    const uint32_t sbase = smem_u32(dsm);

    const size_t qoff = ((size_t)(b * 1024 + f0) * 16 + n) * 64;
    const size_t koffg = ((size_t)(b * 1024 + t0) * 16 + n) * 64;

#pragma unroll
    for (int l = 0; l < 4; l++) {
        int idx = tid + l * 256;
        int m = idx >> 3, hc = (idx & 7) << 3;
        size_t so = (size_t)m * 1024 + hc;
        uint32_t doff = (uint32_t)(m * 72 + hc) * 2;
        cp16(sbase + doff,            g_q + qoff + so);
        cp16(sbase + 9216 * 2 + doff, g_k + koffg + so);
    }
    CP_COMMIT();
    CP_WAIT(0);
    __syncthreads();

    float c[2][8][4];
#pragma unroll
    for (int i = 0; i < 2; i++)
#pragma unroll
        for (int j = 0; j < 8; j++)
#pragma unroll
            for (int q = 0; q < 4; q++) c[i][j][q] = 0.0f;

    const int lrow = lane & 15, koff = (lane >> 4) << 3;
#pragma unroll
    for (int ks = 0; ks < 4; ks++) {
        uint32_t a[2][4];
#pragma unroll
        for (int mf = 0; mf < 2; mf++) {
            uint32_t off = (uint32_t)((wm * 32 + mf * 16 + lrow) * 72 + ks * 16 + koff) * 2;
            ldsm_x4(a[mf], sbase + off);
        }
#pragma unroll
        for (int g = 0; g < 4; g++) {
            uint32_t rh[4];
            uint32_t off = (uint32_t)((wn * 64 + g * 16 + lrow) * 72 + ks * 16 + koff) * 2;
            ldsm_x4(rh, sbase + 9216 * 2 + off);
            uint32_t b0[2] = {rh[0], rh[2]}, b1[2] = {rh[1], rh[3]};
#pragma unroll
            for (int mf = 0; mf < 2; mf++) {
                mma_bf16(c[mf][g * 2 + 0], a[mf], b0);
                mma_bf16(c[mf][g * 2 + 1], a[mf], b1);
            }
        }
    }

    __nv_bfloat16* out = g_sb + (size_t)z * 1048576;
    const int rbase = f0 + wm * 32 + (lane >> 2);
    const int cbase = t0 + wn * 64 + (lane & 3) * 2;
#pragma unroll
    for (int mf = 0; mf < 2; mf++) {
#pragma unroll
        for (int nf = 0; nf < 8; nf++) {
            int r = rbase + mf * 16, cc = cbase + nf * 8;
            *(__nv_bfloat162*)(out + (size_t)r * 1024 + cc) =
                __halves2bfloat162(__float2bfloat16(c[mf][nf][0] * 0.125f),
                                   __float2bfloat16(c[mf][nf][1] * 0.125f));
            *(__nv_bfloat162*)(out + (size_t)(r + 8) * 1024 + cc) =
                __halves2bfloat162(__float2bfloat16(c[mf][nf][2] * 0.125f),
                                   __float2bfloat16(c[mf][nf][3] * 0.125f));
        }
    }
}

// ---------------------------------------------------------------------------
// fused premix(MMA) -> mask -> softmax -> postmix(FFMA).  b = blockIdx.y + b0.
// smem: sbf bf16[16][1032] (33024B) | s f32[16][1028] (65792B) | smadd[1024] (4096B)
// ---------------------------------------------------------------------------
#define SW 1028
#define SBFS 1032
__global__ __launch_bounds__(256)
void mix_softmax_kernel(const int* __restrict__ amask,
                        const float* __restrict__ pre,
                        const float* __restrict__ post, int b0) {
    extern __shared__ char dynsm[];
    __nv_bfloat16* sbf = (__nv_bfloat16*)dynsm;
    float* s     = (float*)(dynsm + 33024);
    float* smadd = (float*)(dynsm + 33024 + 65792);
    __shared__ float wpre[256], wpost[256], sinv[16];
    const int tid = threadIdx.x, lane = tid & 31, warp = tid >> 5;
    const int f = blockIdx.x, b = blockIdx.y + b0;

    wpre[tid]  = pre[tid];
    wpost[tid] = post[tid];

    const size_t rowbase = ((size_t)(b * 16) * 1024 + f) * 1024;
    const uint32_t sbf_u32 = smem_u32(sbf);

#pragma unroll
    for (int l = 0; l < 8; l++) {
        int idx = tid + l * 256;
        int n = idx >> 7, ch = idx & 127;
        cp16(sbf_u32 + (uint32_t)(n * SBFS + ch * 8) * 2,
             g_sb + rowbase + (size_t)n * 1048576 + ch * 8);
    }
    CP_COMMIT();

    {
        int4 mv = *(const int4*)(amask + ((size_t)b * 1024 + f) * 1024 + tid * 4);
        smadd[tid * 4 + 0] = (1.0f - (float)mv.x) * -10000.0f;
        smadd[tid * 4 + 1] = (1.0f - (float)mv.y) * -10000.0f;
        smadd[tid * 4 + 2] = (1.0f - (float)mv.z) * -10000.0f;
        smadd[tid * 4 + 3] = (1.0f - (float)mv.w) * -10000.0f;
    }
    CP_WAIT(0);
    __syncthreads();

    // premix via MMA
    {
        const int g = lane >> 2, t4 = lane & 3;
        uint32_t awh[4], awl[4];
#pragma unroll
        for (int q = 0; q < 4; q++) {
            int kk = 2 * t4 + (q >> 1) * 8;
            int rr = g + (q & 1) * 8;
            __nv_bfloat16 h0, l0, h1, l1;
            split_bf16(wpre[kk * 16 + rr], h0, l0);
            split_bf16(wpre[(kk + 1) * 16 + rr], h1, l1);
            __nv_bfloat162 ph = __halves2bfloat162(h0, h1), pl = __halves2bfloat162(l0, l1);
            awh[q] = *(uint32_t*)&ph;
            awl[q] = *(uint32_t*)&pl;
        }
        const int t0 = warp * 128;
#pragma unroll
        for (int blk = 0; blk < 8; blk++) {
            int tb = t0 + blk * 16;
            uint32_t bfr[4];
            ldsm_x4_t(bfr, sbf_u32 + (uint32_t)((lane & 15) * SBFS + tb + ((lane >> 4) << 3)) * 2);
#pragma unroll
            for (int h = 0; h < 2; h++) {
                int cb = tb + h * 8 + 2 * t4;
                float m0 = smadd[cb], m1 = smadd[cb + 1];
                float c[4] = {m0, m1, m0, m1};
                mma_bf16(c, awh, bfr + h * 2);
                mma_bf16(c, awl, bfr + h * 2);
                *(float2*)&s[g * SW + cb]       = make_float2(c[0], c[1]);
                *(float2*)&s[(g + 8) * SW + cb] = make_float2(c[2], c[3]);
            }
        }
    }
    __syncthreads();

    // softmax
#pragma unroll
    for (int r = 0; r < 2; r++) {
        int l = warp * 2 + r;
        float m = -1e30f;
        for (int it = lane; it < 1024; it += 32) m = fmaxf(m, s[l * SW + it]);
#pragma unroll
        for (int o = 16; o > 0; o >>= 1) m = fmaxf(m, __shfl_xor_sync(0xffffffffu, m, o));
        float sum = 0.0f;
        for (int it = lane; it < 1024; it += 32) {
            float e = __expf(s[l * SW + it] - m);
            s[l * SW + it] = e;
            sum += e;
        }
#pragma unroll
        for (int o = 16; o > 0; o >>= 1) sum += __shfl_xor_sync(0xffffffffu, sum, o);
        if (lane == 0) sinv[l] = 1.0f / sum;
    }
    __syncthreads();

    // postmix (scalar FFMA), write split-bf16 P
#pragma unroll
    for (int c = 0; c < 2; c++) {
        int t = (tid + c * 256) * 2;
        float x0[16], x1[16];
#pragma unroll
        for (int n = 0; n < 16; n++) {
            x0[n] = s[n * SW + t] * sinv[n];
            x1[n] = s[n * SW + t + 1] * sinv[n];
        }
#pragma unroll
        for (int l = 0; l < 16; l++) {
            float y0 = 0.0f, y1 = 0.0f;
#pragma unroll
            for (int n = 0; n < 16; n++) {
                y0 = fmaf(x0[n], wpost[n * 16 + l], y0);
                y1 = fmaf(x1[n], wpost[n * 16 + l], y1);
            }
            __nv_bfloat16 h0, l0, h1, l1;
            split_bf16(y0, h0, l0); split_bf16(y1, h1, l1);
            size_t base = rowbase + (size_t)l * 1048576 + t;
            *(__nv_bfloat162*)(g_p_hi + base) = __halves2bfloat162(h0, h1);
            *(__nv_bfloat162*)(g_p_lo + base) = __halves2bfloat162(l0, l1);
        }
    }
}

// ---------------------------------------------------------------------------
// pv: ctx = P @ V, bf16x3 MMA.  zbase = b0*16.  3-stage cp.async.
// ---------------------------------------------------------------------------
#define PV_PS 14848
__device__ __forceinline__ void pv_stage(uint32_t sb, size_t pbase, size_t vbase,
                                         int k0, int tid) {
#pragma unroll
    for (int l = 0; l < 2; l++) {
        int idx = tid + l * 256;
        int m = idx >> 2, tc = (idx & 3) << 3;
        size_t so = pbase + (size_t)m * 1024 + k0 + tc;
        cp16(sb + (uint32_t)(m * 40 + tc) * 2, g_p_hi + so);
        cp16(sb + (uint32_t)(5120 + m * 40 + tc) * 2, g_p_lo + so);
    }
    {
        int tr = tid >> 3, hc = (tid & 7) << 3;
        size_t so = vbase + (size_t)(k0 + tr) * 1024 + hc;
        cp16(sb + (uint32_t)(10240 + tr * 72 + hc) * 2, g_v_hi + so);
        cp16(sb + (uint32_t)(12544 + tr * 72 + hc) * 2, g_v_lo + so);
    }
}

__global__ __launch_bounds__(256)
void pv_mma(int zbase) {
    extern __shared__ __nv_bfloat16 dsm[];
    const int tid = threadIdx.x, lane = tid & 31, warp = tid >> 5;
    const int wm = warp >> 1, wn = warp & 1;
    const int z = blockIdx.y + zbase, b = z >> 4, n = z & 15;
    const int f0 = blockIdx.x * 128;
    const uint32_t sbase = smem_u32(dsm);

    const size_t pbase = (size_t)z * 1048576 + (size_t)f0 * 1024;
    const size_t vbase = (size_t)(b * 1024) * 1024 + (size_t)n * 64;

    float c[2][4][4];
#pragma unroll
    for (int i = 0; i < 2; i++)
#pragma unroll
        for (int j = 0; j < 4; j++)
#pragma unroll
            for (int q = 0; q < 4; q++) c[i][j][q] = 0.0f;

    pv_stage(sbase,              pbase, vbase, 0,  tid);
    CP_COMMIT();
    pv_stage(sbase + PV_PS * 2,  pbase, vbase, 32, tid);
    CP_COMMIT();

    const int lrow = lane & 15, koff = (lane >> 4) << 3;
    int st = 0;
    for (int k0 = 0; k0 < 1024; k0 += 32) {
        if (k0 + 32 < 1024) { CP_WAIT(1); } else { CP_WAIT(0); }
        __syncthreads();

        const uint32_t sb = sbase + (uint32_t)st * PV_PS * 2;
#pragma unroll
        for (int ks = 0; ks < 2; ks++) {
            uint32_t ahi[2][4], alo[2][4];
#pragma unroll
            for (int mf = 0; mf < 2; mf++) {
                uint32_t off = (uint32_t)((wm * 32 + mf * 16 + lrow) * 40 + ks * 16 + koff) * 2;
                ldsm_x4(ahi[mf], sb + off);
                ldsm_x4(alo[mf], sb + 5120 * 2 + off);
            }
#pragma unroll
            for (int g = 0; g < 2; g++) {
                uint32_t bh[4], bl[4];
                uint32_t off = (uint32_t)((ks * 16 + lrow) * 72 + wn * 32 + g * 16 + koff) * 2;
                ldsm_x4_t(bh, sb + 10240 * 2 + off);
                ldsm_x4_t(bl, sb + 12544 * 2 + off);
#pragma unroll
                for (int h = 0; h < 2; h++) {
                    int nf = g * 2 + h;
#pragma unroll
                    for (int mf = 0; mf < 2; mf++) {
                        mma_bf16(c[mf][nf], ahi[mf], bh + h * 2);
                        mma_bf16(c[mf][nf], ahi[mf], bl + h * 2);
                        mma_bf16(c[mf][nf], alo[mf], bh + h * 2);
                    }
                }
            }
        }
        if (k0 + 64 < 1024) {
            int nst = (st + 2 > 2) ? (st - 1) : (st + 2);
            pv_stage(sbase + (uint32_t)nst * PV_PS * 2, pbase, vbase, k0 + 64, tid);
            CP_COMMIT();
        }
        st = (st == 2) ? 0 : st + 1;
    }

    const int rbase = f0 + wm * 32 + (lane >> 2);
    const int cbase = wn * 32 + (lane & 3) * 2;
#pragma unroll
    for (int mf = 0; mf < 2; mf++) {
#pragma unroll
        for (int nf = 0; nf < 4; nf++) {
            int r = rbase + mf * 16, cc = cbase + nf * 8;
            size_t o0 = ((size_t)(b * 1024 + r) * 16 + n) * 64 + cc;
            size_t o1 = ((size_t)(b * 1024 + r + 8) * 16 + n) * 64 + cc;
            __nv_bfloat16 h0, l0, h1, l1;
            split_bf16(c[mf][nf][0], h0, l0); split_bf16(c[mf][nf][1], h1, l1);
            *(__nv_bfloat162*)(g_c_hi + o0) = __halves2bfloat162(h0, h1);
            *(__nv_bfloat162*)(g_c_lo + o0) = __halves2bfloat162(l0, l1);
            split_bf16(c[mf][nf][2], h0, l0); split_bf16(c[mf][nf][3], h1, l1);
            *(__nv_bfloat162*)(g_c_hi + o1) = __halves2bfloat162(h0, h1);
            *(__nv_bfloat162*)(g_c_lo + o1) = __halves2bfloat162(l0, l1);
        }
    }
}

// ---------------------------------------------------------------------------
extern "C" void kernel_launch(void* const* d_in, const int* in_sizes, int n_in,
                              void* d_out, int out_size) {
    const float* from  = (const float*)d_in[0];
    const float* to    = (const float*)d_in[1];
    const int*   amask = (const int*)d_in[2];
    const float* wq    = (const float*)d_in[3];
    const float* bq    = (const float*)d_in[4];
    const float* wk    = (const float*)d_in[5];
    const float* bk    = (const float*)d_in[6];
    const float* wv    = (const float*)d_in[7];
    const float* bv    = (const float*)d_in[8];
    const float* pre   = (const float*)d_in[9];
    const float* post  = (const float*)d_in[10];
    const float* wo    = (const float*)d_in[11];
    const float* bo    = (const float*)d_in[12];
    float* out = (float*)d_out;

    void *fh, *th, *tl, *qwh, *kwh, *vwh, *vwl, *owh, *owl;
    void *qp, *kp, *vh, *vl, *ch, *cl;
    cudaGetSymbolAddress(&fh, g_from_hi);
    cudaGetSymbolAddress(&th, g_to_hi);   cudaGetSymbolAddress(&tl, g_to_lo);
    cudaGetSymbolAddress(&qwh, g_wq_hi);
    cudaGetSymbolAddress(&kwh, g_wk_hi);
    cudaGetSymbolAddress(&vwh, g_wv_hi);  cudaGetSymbolAddress(&vwl, g_wv_lo);
    cudaGetSymbolAddress(&owh, g_wo_hi);  cudaGetSymbolAddress(&owl, g_wo_lo);
    cudaGetSymbolAddress(&qp, g_q);       cudaGetSymbolAddress(&kp, g_k);
    cudaGetSymbolAddress(&vh, g_v_hi);    cudaGetSymbolAddress(&vl, g_v_lo);
    cudaGetSymbolAddress(&ch, g_c_hi);    cudaGetSymbolAddress(&cl, g_c_lo);

    const int GEMM3_SMEM = 3 * 18944 * 2;     // 113664 B
    const int GEMM1_SMEM = 3 * 9472 * 2;      // 56832 B
    const int QK_SMEM    = 18432 * 2;         // 36864 B
    const int PV_SMEM    = 3 * PV_PS * 2;     // 89088 B
    const int SMX_SMEM   = 33024 + 65792 + 4096;  // 102912 B -> 2 CTAs/SM
    cudaFuncSetAttribute((const void*)gemm_bf16<0, 3, false>, cudaFuncAttributeMaxDynamicSharedMemorySize, GEMM3_SMEM);
    cudaFuncSetAttribute((const void*)gemm_bf16<1, 3, false>, cudaFuncAttributeMaxDynamicSharedMemorySize, GEMM3_SMEM);
    cudaFuncSetAttribute((const void*)gemm_bf16<2, 1, true>,  cudaFuncAttributeMaxDynamicSharedMemorySize, GEMM1_SMEM);
    cudaFuncSetAttribute((const void*)qk_mma,                 cudaFuncAttributeMaxDynamicSharedMemorySize, QK_SMEM);
    cudaFuncSetAttribute((const void*)pv_mma,                 cudaFuncAttributeMaxDynamicSharedMemorySize, PV_SMEM);
    cudaFuncSetAttribute((const void*)mix_softmax_kernel,     cudaFuncAttributeMaxDynamicSharedMemorySize, SMX_SMEM);

    // streams + events (created once on the first, uncaptured correctness call)
    static cudaStream_t s2 = nullptr, s3 = nullptr;
    static cudaEvent_t evSplit = nullptr, evQK = nullptr, evV = nullptr, evB = nullptr;
    if (s2 == nullptr) {
        cudaStreamCreateWithFlags(&s2, cudaStreamNonBlocking);
        cudaStreamCreateWithFlags(&s3, cudaStreamNonBlocking);
        cudaEventCreateWithFlags(&evSplit, cudaEventDisableTiming);
        cudaEventCreateWithFlags(&evQK, cudaEventDisableTiming);
        cudaEventCreateWithFlags(&evV, cudaEventDisableTiming);
        cudaEventCreateWithFlags(&evB, cudaEventDisableTiming);
    }

    split_inputs<<<8192, 256>>>((const float4*)from, (const float4*)to,
                                (uint2*)fh, (uint2*)th, (uint2*)tl);
    split_weights<<<4096, 256>>>((const float4*)wq, (const float4*)wk,
                                 (const float4*)wv, (const float4*)wo,
                                 (uint2*)qwh, (uint2*)kwh,
                                 (uint2*)vwh, (uint2*)vwl,
                                 (uint2*)owh, (uint2*)owl);
    cudaEventRecord(evSplit, 0);

    // V projection on s3 (feeds pv on both chains)
    cudaStreamWaitEvent(s3, evSplit, 0);
    gemm_bf16<1, 3, false><<<dim3(8, 32), 256, GEMM3_SMEM, s3>>>(
        (const __nv_bfloat16*)th, (const __nv_bfloat16*)tl,
        (const __nv_bfloat16*)vwh, (const __nv_bfloat16*)vwl, bv,
        nullptr, (__nv_bfloat16*)vh, (__nv_bfloat16*)vl,
        nullptr, nullptr, nullptr, nullptr);
    cudaEventRecord(evV, s3);

    // merged Q+K projections on main
    gemm_bf16<2, 1, true><<<dim3(8, 32, 2), 256, GEMM1_SMEM>>>(
        (const __nv_bfloat16*)fh, nullptr,
        (const __nv_bfloat16*)qwh, nullptr, bq,
        nullptr, (__nv_bfloat16*)qp, nullptr,
        (const __nv_bfloat16*)th, (const __nv_bfloat16*)kwh, bk, (__nv_bfloat16*)kp);
    cudaEventRecord(evQK, 0);

    // ---- chain A (main stream): batches 0,1 ----
    qk_mma<<<dim3(8, 8, 32), 256, QK_SMEM>>>(0);
    mix_softmax_kernel<<<dim3(1024, 2), 256, SMX_SMEM>>>(amask, pre, post, 0);
    cudaStreamWaitEvent((cudaStream_t)0, evV, 0);
    pv_mma<<<dim3(8, 32), 256, PV_SMEM>>>(0);
    gemm_bf16<0, 3, false><<<dim3(8, 16), 256, GEMM3_SMEM>>>(
        (const __nv_bfloat16*)ch, (const __nv_bfloat16*)cl,
        (const __nv_bfloat16*)owh, (const __nv_bfloat16*)owl, bo,
        out, nullptr, nullptr,
        nullptr, nullptr, nullptr, nullptr);

    // ---- chain B (s2): batches 2,3 ----
    cudaStreamWaitEvent(s2, evQK, 0);
    qk_mma<<<dim3(8, 8, 32), 256, QK_SMEM, s2>>>(32);
    mix_softmax_kernel<<<dim3(1024, 2), 256, SMX_SMEM, s2>>>(amask, pre, post, 2);
    cudaStreamWaitEvent(s2, evV, 0);
    pv_mma<<<dim3(8, 32), 256, PV_SMEM, s2>>>(32);
    gemm_bf16<0, 3, false><<<dim3(8, 16), 256, GEMM3_SMEM, s2>>>(
        (const __nv_bfloat16*)ch + (size_t)2048 * 1024,
        (const __nv_bfloat16*)cl + (size_t)2048 * 1024,
        (const __nv_bfloat16*)owh, (const __nv_bfloat16*)owl, bo,
        out + (size_t)2048 * 1024, nullptr, nullptr,
        nullptr, nullptr, nullptr, nullptr);
    cudaEventRecord(evB, s2);

    // join: main stream must not complete before chain B's output is written
    cudaStreamWaitEvent((cudaStream_t)0, evB, 0);
}